// round 6
// baseline (speedup 1.0000x reference)
#include <cuda_runtime.h>
#include <math.h>

#define BSZ    65536
#define TT     31
#define HIDN   128
#define NVOCAB 19
#define NCONST 40
#define INSZ   133
#define SLOTS  128
#define NTH    512
#define NBLK   152

#define OUT_CV  2031616   // BSZ*TT
#define OUT_LP  4063232   // 2*BSZ*TT
#define OUT_TOT 4194304

typedef unsigned long long u64;

// shared float layout
#define S_WHH  0            // float4[kq=32][j=128]: {W_hh[j][4kq..4kq+3]}
#define S_TOKP 16384        // float4[kq=32][v=32]
#define S_CON  20480        // [k][64] const head
#define S_H    28672        // [128][128]
#define S_WX   45056        // [f=9][j=128]
#define S_BSUM 46208        // 128
#define S_BTOK 46336        // 32
#define S_BCON 46368        // 64
#define S_LP   46432        // 128
#define S_NF   46560
// int region
#define SI_POS  0
#define SI_SP   128
#define SI_ACT  256
#define SI_T    384
#define SI_GROW 512
#define SI_STK  640         // 128 x 8
#define SI_LIST 1664
#define SI_DEAD 1792
#define SI_WD   1920        // 16 per-warp descriptors
#define SI_CNT  1936        // [0]=A  [1]=base
#define SI_N    1940
#define SMEM_BYTES ((S_NF + SI_N) * 4)

#define FULLM 0xffffffffu

__device__ float g_WihT[INSZ * HIDN];          // [c][j]
__device__ float g_ACC[NBLK * SLOTS * HIDN];   // per-block per-slot acc
__device__ int   g_next;

__device__ __forceinline__ u64 ffma2(u64 a, u64 b, u64 c) {
    u64 d;
    asm("fma.rn.f32x2 %0, %1, %2, %3;" : "=l"(d) : "l"(a), "l"(b), "l"(c));
    return d;
}
__device__ __forceinline__ float f2lo(u64 v) { return __uint_as_float((unsigned)v); }
__device__ __forceinline__ float f2hi(u64 v) { return __uint_as_float((unsigned)(v >> 32)); }

__device__ __forceinline__ void lds2(u64& a, u64& b, const float* p) {
    unsigned addr = (unsigned)__cvta_generic_to_shared(p);
    asm("ld.shared.v2.b64 {%0, %1}, [%2];" : "=l"(a), "=l"(b) : "r"(addr));
}

__device__ __forceinline__ float gumbelf(float u) {
    float inner = -logf(u + 1e-9f);
    return -logf(inner + 1e-9f);
}
__device__ __forceinline__ float wmaxf(float v) {
#pragma unroll
    for (int o = 16; o; o >>= 1) v = fmaxf(v, __shfl_xor_sync(FULLM, v, o));
    return v;
}
__device__ __forceinline__ float wsumf(float v) {
#pragma unroll
    for (int o = 16; o; o >>= 1) v += __shfl_xor_sync(FULLM, v, o);
    return v;
}
__device__ __forceinline__ void wargmax(float& s, int& i, float& lp) {
#pragma unroll
    for (int o = 16; o; o >>= 1) {
        float s2 = __shfl_xor_sync(FULLM, s, o);
        int   i2 = __shfl_xor_sync(FULLM, i, o);
        float l2 = __shfl_xor_sync(FULLM, lp, o);
        if (s2 > s || (s2 == s && i2 < i)) { s = s2; i = i2; lp = l2; }
    }
}

// One step for up to 8 rows. grp[] is padded with grp[0] duplicates beyond rcnt:
// Phase A recomputes identical h for the duplicate (idempotent smem write), all
// state-mutating work (C2) is gated by i < rcnt.
template<bool FRESH>
__device__ __forceinline__ void step_group8(float* sm, int* si, float* gacc,
                           const float* __restrict__ noise_tok,
                           const float* __restrict__ noise_c,
                           float* __restrict__ out,
                           const int* grp, int rcnt, int lane)
{
    // noise prefetch (overlaps GEMV)
    float u_t[8];
#pragma unroll
    for (int i = 0; i < 8; i++) {
        int row = grp[i];
        int tti = FRESH ? 0 : si[SI_T + row];
        int gri = si[SI_GROW + row];
        long long bt = (long long)tti * BSZ + gri;
        u_t[i] = (lane < NVOCAB) ? __ldg(&noise_tok[bt * NVOCAB + lane]) : 0.5f;
    }

    if (!FRESH) {
        // Phase A: z = W_hh*h, two m-half passes so 8 rows share each weight read
        float hn[8][4];
#pragma unroll
        for (int pass = 0; pass < 2; pass++) {
            float af[8][2];
#pragma unroll
            for (int i = 0; i < 8; i++)
#pragma unroll
                for (int mm = 0; mm < 2; mm++)
                    af[i][mm] = gacc[grp[i] * HIDN + lane + 32 * (2 * pass + mm)];
            u64 zp[8][2];
#pragma unroll
            for (int i = 0; i < 8; i++) { zp[i][0] = 0ull; zp[i][1] = 0ull; }
#pragma unroll 2
            for (int kq = 0; kq < 32; kq++) {
                u64 h01[8], h23[8];
#pragma unroll
                for (int i = 0; i < 8; i++)
                    lds2(h01[i], h23[i], sm + S_H + grp[i] * HIDN + 4 * kq);
#pragma unroll
                for (int mm = 0; mm < 2; mm++) {
                    u64 w01, w23;
                    lds2(w01, w23, sm + S_WHH + (kq * 128 + lane + 32 * (2 * pass + mm)) * 4);
#pragma unroll
                    for (int i = 0; i < 8; i++) {
                        zp[i][mm] = ffma2(h01[i], w01, zp[i][mm]);
                        zp[i][mm] = ffma2(h23[i], w23, zp[i][mm]);
                    }
                }
            }
#pragma unroll
            for (int i = 0; i < 8; i++)
#pragma unroll
                for (int mm = 0; mm < 2; mm++) {
                    float z = f2lo(zp[i][mm]) + f2hi(zp[i][mm]);
                    hn[i][2 * pass + mm] = tanhf(z + af[i][mm]);
                }
        }
        __syncwarp();
#pragma unroll
        for (int i = 0; i < 8; i++)
#pragma unroll
            for (int m = 0; m < 4; m++)
                sm[S_H + grp[i] * HIDN + lane + 32 * m] = hn[i][m];
        __syncwarp();
    }

    // Phase B: token head logits (lane = vocab index)
    u64 tkp[8];
#pragma unroll
    for (int i = 0; i < 8; i++) tkp[i] = 0ull;
#pragma unroll 4
    for (int kq = 0; kq < 32; kq++) {
        u64 w01, w23;
        lds2(w01, w23, sm + S_TOKP + (kq * 32 + lane) * 4);
#pragma unroll
        for (int i = 0; i < 8; i++) {
            u64 h01, h23;
            lds2(h01, h23, sm + S_H + grp[i] * HIDN + 4 * kq);
            tkp[i] = ffma2(h01, w01, tkp[i]);
            tkp[i] = ffma2(h23, w23, tkp[i]);
        }
    }
    float btok = sm[S_BTOK + lane];
    const float NEGINF = -INFINITY;

    // Phase C1: batched softmax + Gumbel argmax (8-way ILP on chains)
    float ltok[8];
#pragma unroll
    for (int i = 0; i < 8; i++) {
        int pi = FRESH ? 0 : si[SI_POS + grp[i]];
        float l = NEGINF;
        if (lane < NVOCAB) {
            l = f2lo(tkp[i]) + f2hi(tkp[i]) + btok;
            if (pi >= 15 && lane < 6) l = NEGINF;
        }
        ltok[i] = l;
    }
    float mx[8];
#pragma unroll
    for (int i = 0; i < 8; i++) mx[i] = ltok[i];
#pragma unroll
    for (int o = 16; o; o >>= 1)
#pragma unroll
        for (int i = 0; i < 8; i++)
            mx[i] = fmaxf(mx[i], __shfl_xor_sync(FULLM, mx[i], o));
    float sme[8];
#pragma unroll
    for (int i = 0; i < 8; i++)
        sme[i] = (lane < NVOCAB) ? expf(ltok[i] - mx[i]) : 0.f;
#pragma unroll
    for (int o = 16; o; o >>= 1)
#pragma unroll
        for (int i = 0; i < 8; i++)
            sme[i] += __shfl_xor_sync(FULLM, sme[i], o);
    float sc[8], lpw[8];
    int ci[8];
#pragma unroll
    for (int i = 0; i < 8; i++) {
        float lse = logf(sme[i]);
        float lpt = ltok[i] - mx[i] - lse;
        sc[i]  = lpt + gumbelf(u_t[i]);
        ci[i]  = lane;
        lpw[i] = lpt;
    }
#pragma unroll
    for (int o = 16; o; o >>= 1) {
#pragma unroll
        for (int i = 0; i < 8; i++) {
            float s2 = __shfl_xor_sync(FULLM, sc[i], o);
            int   i2 = __shfl_xor_sync(FULLM, ci[i], o);
            float l2 = __shfl_xor_sync(FULLM, lpw[i], o);
            if (s2 > sc[i] || (s2 == sc[i] && i2 < ci[i])) {
                sc[i] = s2; ci[i] = i2; lpw[i] = l2;
            }
        }
    }

    // Phase C2: rare const head + bookkeeping (gated by rcnt)
#pragma unroll
    for (int i = 0; i < 8; i++) {
        if (i >= rcnt) break;
        int row = grp[i];
        int pi  = FRESH ? 0 : si[SI_POS + row];
        int tti = FRESH ? 0 : si[SI_T + row];
        int gri = si[SI_GROW + row];
        int choice = ci[i];
        float lp_tok = lpw[i];

        bool is_const = (choice == 18);
        float lp_c = 0.f; int cchoice = 0;
        if (is_const) {   // warp-uniform
            float2 co = make_float2(0.f, 0.f);
#pragma unroll 8
            for (int k4 = 0; k4 < 32; k4++) {
                float4 hv = *(const float4*)(sm + S_H + row * HIDN + 4 * k4);
#pragma unroll
                for (int b = 0; b < 4; b++) {
                    float2 wc = *(const float2*)(sm + S_CON + (4 * k4 + b) * 64 + 2 * lane);
                    float hk = (b == 0) ? hv.x : (b == 1) ? hv.y : (b == 2) ? hv.z : hv.w;
                    co.x = fmaf(hk, wc.x, co.x);
                    co.y = fmaf(hk, wc.y, co.y);
                }
            }
            long long bt = (long long)tti * BSZ + gri;
            float2 uc = make_float2(0.f, 0.f);
            if (lane < 20) uc = *(const float2*)(&noise_c[bt * NCONST + 2 * lane]);
            float bc0 = sm[S_BCON + 2 * lane];
            float bc1 = sm[S_BCON + 2 * lane + 1];
            float la = (lane < 20) ? (co.x + bc0) : NEGINF;
            float lb = (lane < 20) ? (co.y + bc1) : NEGINF;
            float mc   = wmaxf(fmaxf(la, lb));
            float ec   = (lane < 20) ? (expf(la - mc) + expf(lb - mc)) : 0.f;
            float lsec = logf(wsumf(ec));
            float lpa = la - mc - lsec;
            float lpb = lb - mc - lsec;
            float sa = lpa + gumbelf(uc.x);
            float sb = lpb + gumbelf(uc.y);
            float s_l, lp_l; int i_l;
            if (sb > sa) { s_l = sb; i_l = 2 * lane + 1; lp_l = lpb; }
            else         { s_l = sa; i_l = 2 * lane;     lp_l = lpa; }
            wargmax(s_l, i_l, lp_l);
            cchoice = i_l; lp_c = lp_l;
        }

        if (lane == 0) {
            float lpn = (FRESH ? 0.f : sm[S_LP + row]) + lp_tok + (is_const ? lp_c : 0.f);
            out[gri * TT + pi] = (float)choice;
            if (is_const) out[OUT_CV + gri * TT + pi] = -10.f + 0.5f * (float)cchoice;
            int arity = (choice < 4) ? 2 : ((choice < 6) ? 1 : 0);
            int sp = FRESH ? 0 : si[SI_SP + row];
            if (arity == 2) {
                int wsp = sp < 7 ? sp : 7;
                si[SI_STK + row * 8 + wsp] = 2 * pi + 2;
            }
            int sp1 = sp + (arity == 2 ? 1 : 0);
            int nxt, sp2;
            if (arity != 0) { nxt = 2 * pi + 1; sp2 = sp1; }
            else {
                int ridx = sp1 - 1; if (ridx < 0) ridx = 0; if (ridx > 7) ridx = 7;
                nxt = (sp1 > 0) ? si[SI_STK + row * 8 + ridx] : -1;
                sp2 = (sp1 > 0) ? sp1 - 1 : 0;
            }
            if (nxt > TT - 1) nxt = -1;
            if (nxt >= 0) {
                sm[S_LP + row]   = lpn;
                si[SI_POS + row] = nxt;
                si[SI_SP + row]  = sp2;
                si[SI_T + row]   = tti + 1;
            } else {
                si[SI_ACT + row] = 0;
                out[OUT_LP + gri] = lpn;
            }
        }
        // fold chosen token code into acc (global, L1/L2 resident)
        if (choice & 15) {
            int cb = 4 * pi;
#pragma unroll
            for (int m = 0; m < 4; m++) {
                int j = lane + 32 * m;
                float a = gacc[row * HIDN + j];
#pragma unroll
                for (int b = 0; b < 4; b++)
                    if (choice & (1 << b))
                        a += __ldg(&g_WihT[(cb + b) * HIDN + j]);
                gacc[row * HIDN + j] = a;
            }
        }
    }
}

__global__ void __launch_bounds__(NTH, 1)
rnn_main(const float* __restrict__ x,
         const float* __restrict__ noise_tok,
         const float* __restrict__ noise_c,
         const float* __restrict__ W_ih,
         const float* __restrict__ W_hh,
         const float* __restrict__ b_ih,
         const float* __restrict__ b_hh,
         const float* __restrict__ W_out,
         const float* __restrict__ b_out,
         const float* __restrict__ W_c,
         const float* __restrict__ b_c,
         float* __restrict__ out)
{
    extern __shared__ float sm[];
    int* si = (int*)(sm + S_NF);
    int tid = threadIdx.x;
    int w = tid >> 5, lane = tid & 31;
    float* gacc = g_ACC + (long long)blockIdx.x * SLOTS * HIDN;

    // ---- stage weights ----
    {   // W_hh k-quads
        const float4* src = (const float4*)W_hh;   // [j][32]
        float4* dst = (float4*)(sm + S_WHH);
        for (int idx = tid; idx < 32 * 128; idx += NTH) {
            int kq = idx >> 7, j = idx & 127;
            dst[kq * 128 + j] = src[j * 32 + kq];
        }
    }
    {   // token head k-quads (zero-pad v 19..31)
        float4* dst = (float4*)(sm + S_TOKP);
        const float4 z4 = make_float4(0.f, 0.f, 0.f, 0.f);
        const float4* src = (const float4*)W_out;  // [v][32]
        for (int idx = tid; idx < 32 * 32; idx += NTH) {
            int kq = idx >> 5, v = idx & 31;
            dst[kq * 32 + v] = (v < NVOCAB) ? src[v * 32 + kq] : z4;
        }
    }
    for (int idx = tid; idx < HIDN * 64; idx += NTH) sm[S_CON + idx] = 0.f;
    __syncthreads();
    for (int idx = tid; idx < NCONST * HIDN; idx += NTH) {
        int c = idx / HIDN, k = idx % HIDN;
        sm[S_CON + k * 64 + c] = W_c[idx];
    }
    for (int idx = tid; idx < 9 * HIDN; idx += NTH) {
        int f = idx >> 7, j = idx & 127;
        sm[S_WX + f * 128 + j] = W_ih[j * INSZ + 124 + f];
    }
    if (tid < HIDN) sm[S_BSUM + tid] = b_ih[tid] + b_hh[tid];
    if (tid < 32) sm[S_BTOK + tid] = (tid < NVOCAB) ? b_out[tid] : 0.f;
    if (tid < 64) sm[S_BCON + tid] = (tid < NCONST) ? b_c[tid] : 0.f;
    if (tid < SLOTS) si[SI_ACT + tid] = 0;
    __syncthreads();

    // ---- persistent work loop ----
    for (;;) {
        if (w == 0) {
            unsigned lt = (1u << lane) - 1u;
            int nold = 0, ndead = 0;
            unsigned mo[4];
            int po[4], pd[4];
#pragma unroll
            for (int c = 0; c < 4; c++) {
                int act = si[SI_ACT + 32 * c + lane];
                unsigned m = __ballot_sync(FULLM, act != 0);
                mo[c] = m; po[c] = nold; pd[c] = ndead;
                nold  += __popc(m);
                ndead += 32 - __popc(m);
            }
            int base = 0;
            if (lane == 0 && ndead > 0) base = atomicAdd(&g_next, ndead);
            base = __shfl_sync(FULLM, base, 0);
            int navail = BSZ - base;
            if (navail < 0) navail = 0;
            if (navail > ndead) navail = ndead;
#pragma unroll
            for (int c = 0; c < 4; c++) {
                int slot = 32 * c + lane;
                unsigned m = mo[c];
                if ((m >> lane) & 1) si[SI_LIST + po[c] + __popc(m & lt)] = slot;
                else                 si[SI_DEAD + pd[c] + __popc(~m & lt)] = slot;
            }
            int n_og = (nold + 7) >> 3;
            int nw_f = 16 - n_og;
            if (lane < 16) {
                int desc = 0;
                if (lane < n_og) {
                    int st = lane * 8;
                    int c  = nold - st; if (c > 8) c = 8;
                    desc = (st << 9) | (c << 1);
                } else if (nw_f > 0 && navail > 0) {
                    int fi = lane - n_og;
                    int q = navail / nw_f, r = navail % nw_f;
                    int c = q + (fi < r ? 1 : 0);
                    int st = fi * q + (fi < r ? fi : r);
                    desc = (st << 9) | (c << 1) | 1;
                }
                si[SI_WD + lane] = desc;
            }
            if (lane == 0) {
                si[SI_CNT]     = nold + navail;
                si[SI_CNT + 1] = base;
            }
        }
        __syncthreads();
        int A = si[SI_CNT];
        if (A == 0) break;
        int rbase = si[SI_CNT + 1];
        int desc  = si[SI_WD + w];
        int cnt   = (desc >> 1) & 0xFF;
        int st    = desc >> 9;

        if (cnt > 0) {
            if (!(desc & 1)) {
                // old rows, groups of up to 8
                int off = 0;
                while (off < cnt) {
                    int k = cnt - off; if (k > 8) k = 8;
                    int grp[8];
#pragma unroll
                    for (int q = 0; q < 8; q++)
                        grp[q] = si[SI_LIST + st + off + (q < k ? q : 0)];
                    step_group8<false>(sm, si, gacc, noise_tok, noise_c, out, grp, k, lane);
                    off += k;
                }
            } else {
                // fresh rows: init then step, chunks of up to 8
                int off = 0;
                float xl = (lane < 9) ? __ldg(&x[(long long)(rbase + st) * 9 + lane]) : 0.f;
                while (off < cnt) {
                    int k = cnt - off; if (k > 8) k = 8;
                    int grp[8];
                    for (int r = 0; r < k; r++) {
                        int slot = si[SI_DEAD + st + off + r];
                        grp[r] = slot;
                        int gr = rbase + st + off + r;
                        float xln = (lane < 9 && off + r + 1 < cnt)
                            ? __ldg(&x[(long long)(gr + 1) * 9 + lane]) : 0.f;
#pragma unroll
                        for (int m = 0; m < 4; m++) {
                            int j = lane + 32 * m;
                            float a = sm[S_BSUM + j];
#pragma unroll
                            for (int f = 0; f < 9; f++)
                                a = fmaf(__shfl_sync(FULLM, xl, f), sm[S_WX + f * 128 + j], a);
                            gacc[slot * HIDN + j] = a;
                            sm[S_H + slot * HIDN + j] = tanhf(a);
                        }
                        if (lane == 0) {
                            si[SI_ACT + slot]  = 1;
                            si[SI_GROW + slot] = gr;
                        }
                        xl = xln;
                    }
#pragma unroll
                    for (int q = 0; q < 8; q++)
                        if (q >= k) grp[q] = grp[0];
                    __syncwarp();
                    step_group8<true>(sm, si, gacc, noise_tok, noise_c, out, grp, k, lane);
                    off += k;
                }
            }
        }
        __syncthreads();
    }
}

// merged prep + output-init
__global__ void setup_kernel(const float* __restrict__ W_ih, float* __restrict__ out)
{
    int i = blockIdx.x * blockDim.x + threadIdx.x;
    if (i == 0) g_next = 0;
    if (i < INSZ * HIDN) {
        int c = i / HIDN, j = i % HIDN;
        g_WihT[c * HIDN + j] = W_ih[j * INSZ + c];
    }
    float4* o4 = (float4*)out;
    const int n4 = OUT_TOT / 4;
    int stride = gridDim.x * blockDim.x;
    for (int k = i; k < n4; k += stride) {
        float v = (k * 4 < OUT_CV) ? -1.f : 0.f;
        o4[k] = make_float4(v, v, v, v);
    }
}

extern "C" void kernel_launch(void* const* d_in, const int* in_sizes, int n_in,
                              void* d_out, int out_size)
{
    const float* x    = (const float*)d_in[0];
    const float* nt   = (const float*)d_in[1];
    const float* nc   = (const float*)d_in[2];
    const float* wih  = (const float*)d_in[3];
    const float* whh  = (const float*)d_in[4];
    const float* bih  = (const float*)d_in[5];
    const float* bhh  = (const float*)d_in[6];
    const float* wout = (const float*)d_in[7];
    const float* bout = (const float*)d_in[8];
    const float* wc   = (const float*)d_in[9];
    const float* bc   = (const float*)d_in[10];
    float* out = (float*)d_out;

    cudaFuncSetAttribute((const void*)rnn_main,
                         cudaFuncAttributeMaxDynamicSharedMemorySize, SMEM_BYTES);
    setup_kernel<<<512, 256>>>(wih, out);
    rnn_main<<<NBLK, NTH, SMEM_BYTES>>>(x, nt, nc, wih, whh, bih, bhh,
                                        wout, bout, wc, bc, out);
}

// round 7
// speedup vs baseline: 1.0085x; 1.0085x over previous
#include <cuda_runtime.h>
#include <math.h>

#define BSZ    65536
#define TT     31
#define HIDN   128
#define NVOCAB 19
#define NCONST 40
#define INSZ   133
#define SLOTS  64
#define NTH    512
#define NBLK   152

#define OUT_CV  2031616   // BSZ*TT
#define OUT_LP  4063232   // 2*BSZ*TT
#define OUT_TOT 4194304

typedef unsigned long long u64;

// shared float layout
#define S_WHH  0            // float4[kq=32][j=128]: {W_hh[j][4kq..4kq+3]}
#define S_TOKP 16384        // float4[kq=32][v=32]
#define S_CON  20480        // [k][64] const head
#define S_H    28672        // [64][128]
#define S_ACC  36864        // [64][128]
#define S_WX   45056        // [f=9][j=128]
#define S_BSUM 46208        // 128
#define S_BTOK 46336        // 32
#define S_BCON 46368        // 64
#define S_LP   46432        // 64
#define S_NF   46496
// int region
#define SI_POS  0
#define SI_SP   64
#define SI_ACT  128
#define SI_T    192
#define SI_GROW 256
#define SI_STK  320         // 64 x 8
#define SI_LIST 832
#define SI_DEAD 896
#define SI_CNT  960         // [0]=A [1]=navail [2]=base [3]=oldc
#define SI_N    968
#define SMEM_BYTES ((S_NF + SI_N) * 4)

#define FULLM 0xffffffffu

__device__ float g_WihT[INSZ * HIDN];   // [c][j]
__device__ int   g_next;

__device__ __forceinline__ u64 ffma2(u64 a, u64 b, u64 c) {
    u64 d;
    asm("fma.rn.f32x2 %0, %1, %2, %3;" : "=l"(d) : "l"(a), "l"(b), "l"(c));
    return d;
}
__device__ __forceinline__ float f2lo(u64 v) { return __uint_as_float((unsigned)v); }
__device__ __forceinline__ float f2hi(u64 v) { return __uint_as_float((unsigned)(v >> 32)); }

__device__ __forceinline__ void lds2(u64& a, u64& b, const float* p) {
    unsigned addr = (unsigned)__cvta_generic_to_shared(p);
    asm("ld.shared.v2.b64 {%0, %1}, [%2];" : "=l"(a), "=l"(b) : "r"(addr));
}

__device__ __forceinline__ float gumbelf(float u) {
    float inner = -logf(u + 1e-9f);
    return -logf(inner + 1e-9f);
}
__device__ __forceinline__ float wmaxf(float v) {
#pragma unroll
    for (int o = 16; o; o >>= 1) v = fmaxf(v, __shfl_xor_sync(FULLM, v, o));
    return v;
}
__device__ __forceinline__ float wsumf(float v) {
#pragma unroll
    for (int o = 16; o; o >>= 1) v += __shfl_xor_sync(FULLM, v, o);
    return v;
}
__device__ __forceinline__ void wargmax(float& s, int& i, float& lp) {
#pragma unroll
    for (int o = 16; o; o >>= 1) {
        float s2 = __shfl_xor_sync(FULLM, s, o);
        int   i2 = __shfl_xor_sync(FULLM, i, o);
        float l2 = __shfl_xor_sync(FULLM, lp, o);
        if (s2 > s || (s2 == s && i2 < i)) { s = s2; i = i2; lp = l2; }
    }
}

// Executes one decode step for CNT rows; returns survivor bitmask (bit i set
// iff grp[i] is still active afterwards), broadcast to all lanes.
template<int CNT, bool FRESH>
__device__ __forceinline__ unsigned step_group(float* sm, int* si,
                           const float* __restrict__ noise_tok,
                           const float* __restrict__ noise_c,
                           float* __restrict__ out,
                           const int* grp, int lane)
{
    int p[CNT], tt[CNT], gr[CNT];
    float g_t[CNT];
#pragma unroll
    for (int i = 0; i < CNT; i++) {
        int row = grp[i];
        p[i]  = FRESH ? 0 : si[SI_POS + row];
        tt[i] = FRESH ? 0 : si[SI_T + row];
        gr[i] = si[SI_GROW + row];
        long long bt = (long long)tt[i] * BSZ + gr[i];
        float u = (lane < NVOCAB) ? __ldg(&noise_tok[bt * NVOCAB + lane]) : 0.5f;
        g_t[i] = gumbelf(u);   // overlaps GEMV below
    }

    if (!FRESH) {
        // Phase A: z = W_hh * h ; lane owns j = lane + 32m ; k-quad vectorized
        u64 zp[CNT][4];
#pragma unroll
        for (int i = 0; i < CNT; i++)
#pragma unroll
            for (int m = 0; m < 4; m++) zp[i][m] = 0ull;
#pragma unroll 4
        for (int kq = 0; kq < 32; kq++) {
            u64 h01[CNT], h23[CNT];
#pragma unroll
            for (int i = 0; i < CNT; i++)
                lds2(h01[i], h23[i], sm + S_H + grp[i] * HIDN + 4 * kq);
#pragma unroll
            for (int m = 0; m < 4; m++) {
                u64 w01, w23;
                lds2(w01, w23, sm + S_WHH + (kq * 128 + lane + 32 * m) * 4);
#pragma unroll
                for (int i = 0; i < CNT; i++) {
                    zp[i][m] = ffma2(h01[i], w01, zp[i][m]);
                    zp[i][m] = ffma2(h23[i], w23, zp[i][m]);
                }
            }
        }
        float hnew[CNT][4];
#pragma unroll
        for (int i = 0; i < CNT; i++)
#pragma unroll
            for (int m = 0; m < 4; m++) {
                int j = lane + 32 * m;
                float z = f2lo(zp[i][m]) + f2hi(zp[i][m]);
                float a = sm[S_ACC + grp[i] * HIDN + j];
                hnew[i][m] = tanhf(z + a);
            }
        __syncwarp();
#pragma unroll
        for (int i = 0; i < CNT; i++)
#pragma unroll
            for (int m = 0; m < 4; m++)
                sm[S_H + grp[i] * HIDN + lane + 32 * m] = hnew[i][m];
        __syncwarp();
    }
    // (FRESH rows: refill already wrote h = tanh(acc) into S_H)

    // Phase B: token head logits (lane = vocab index), k-quad vectorized
    u64 tkp[CNT];
#pragma unroll
    for (int i = 0; i < CNT; i++) tkp[i] = 0ull;
#pragma unroll 4
    for (int kq = 0; kq < 32; kq++) {
        u64 w01, w23;
        lds2(w01, w23, sm + S_TOKP + (kq * 32 + lane) * 4);
#pragma unroll
        for (int i = 0; i < CNT; i++) {
            u64 h01, h23;
            lds2(h01, h23, sm + S_H + grp[i] * HIDN + 4 * kq);
            tkp[i] = ffma2(h01, w01, tkp[i]);
            tkp[i] = ffma2(h23, w23, tkp[i]);
        }
    }
    float btok = sm[S_BTOK + lane];
    const float NEGINF = -INFINITY;

    // Phase C1: batched softmax + Gumbel argmax across rows
    float ltok[CNT];
#pragma unroll
    for (int i = 0; i < CNT; i++) {
        float l = NEGINF;
        if (lane < NVOCAB) {
            l = f2lo(tkp[i]) + f2hi(tkp[i]) + btok;
            if (p[i] >= 15 && lane < 6) l = NEGINF;
        }
        ltok[i] = l;
    }
    float mx[CNT];
#pragma unroll
    for (int i = 0; i < CNT; i++) mx[i] = ltok[i];
#pragma unroll
    for (int o = 16; o; o >>= 1)
#pragma unroll
        for (int i = 0; i < CNT; i++)
            mx[i] = fmaxf(mx[i], __shfl_xor_sync(FULLM, mx[i], o));
    float sme[CNT];
#pragma unroll
    for (int i = 0; i < CNT; i++)
        sme[i] = (lane < NVOCAB) ? expf(ltok[i] - mx[i]) : 0.f;
#pragma unroll
    for (int o = 16; o; o >>= 1)
#pragma unroll
        for (int i = 0; i < CNT; i++)
            sme[i] += __shfl_xor_sync(FULLM, sme[i], o);
    float sc[CNT], lpw[CNT];
    int ci[CNT];
#pragma unroll
    for (int i = 0; i < CNT; i++) {
        float lse = logf(sme[i]);
        float lpt = ltok[i] - mx[i] - lse;
        sc[i]  = lpt + g_t[i];
        ci[i]  = lane;
        lpw[i] = lpt;
    }
#pragma unroll
    for (int o = 16; o; o >>= 1) {
#pragma unroll
        for (int i = 0; i < CNT; i++) {
            float s2 = __shfl_xor_sync(FULLM, sc[i], o);
            int   i2 = __shfl_xor_sync(FULLM, ci[i], o);
            float l2 = __shfl_xor_sync(FULLM, lpw[i], o);
            if (s2 > sc[i] || (s2 == sc[i] && i2 < ci[i])) {
                sc[i] = s2; ci[i] = i2; lpw[i] = l2;
            }
        }
    }

    // Phase C2: rare const head + bookkeeping
    unsigned alive = 0;
#pragma unroll
    for (int i = 0; i < CNT; i++) {
        int row = grp[i];
        int pi  = p[i];
        int choice = ci[i];
        float lp_tok = lpw[i];

        bool is_const = (choice == 18);
        float lp_c = 0.f; int cchoice = 0;
        if (is_const) {   // warp-uniform
            float2 co = make_float2(0.f, 0.f);
#pragma unroll 8
            for (int k4 = 0; k4 < 32; k4++) {
                float4 hv = *(const float4*)(sm + S_H + row * HIDN + 4 * k4);
#pragma unroll
                for (int b = 0; b < 4; b++) {
                    float2 wc = *(const float2*)(sm + S_CON + (4 * k4 + b) * 64 + 2 * lane);
                    float hk = (b == 0) ? hv.x : (b == 1) ? hv.y : (b == 2) ? hv.z : hv.w;
                    co.x = fmaf(hk, wc.x, co.x);
                    co.y = fmaf(hk, wc.y, co.y);
                }
            }
            long long bt = (long long)tt[i] * BSZ + gr[i];
            float2 uc = make_float2(0.f, 0.f);
            if (lane < 20) uc = *(const float2*)(&noise_c[bt * NCONST + 2 * lane]);
            float bc0 = sm[S_BCON + 2 * lane];
            float bc1 = sm[S_BCON + 2 * lane + 1];
            float la = (lane < 20) ? (co.x + bc0) : NEGINF;
            float lb = (lane < 20) ? (co.y + bc1) : NEGINF;
            float mc   = wmaxf(fmaxf(la, lb));
            float ec   = (lane < 20) ? (expf(la - mc) + expf(lb - mc)) : 0.f;
            float lsec = logf(wsumf(ec));
            float lpa = la - mc - lsec;
            float lpb = lb - mc - lsec;
            float sa = lpa + gumbelf(uc.x);
            float sb = lpb + gumbelf(uc.y);
            float s_l, lp_l; int i_l;
            if (sb > sa) { s_l = sb; i_l = 2 * lane + 1; lp_l = lpb; }
            else         { s_l = sa; i_l = 2 * lane;     lp_l = lpa; }
            wargmax(s_l, i_l, lp_l);
            cchoice = i_l; lp_c = lp_l;
        }

        if (lane == 0) {
            float lpn = (FRESH ? 0.f : sm[S_LP + row]) + lp_tok + (is_const ? lp_c : 0.f);
            out[gr[i] * TT + pi] = (float)choice;
            if (is_const) out[OUT_CV + gr[i] * TT + pi] = -10.f + 0.5f * (float)cchoice;
            int arity = (choice < 4) ? 2 : ((choice < 6) ? 1 : 0);
            int sp = FRESH ? 0 : si[SI_SP + row];
            if (arity == 2) {
                int wsp = sp < 7 ? sp : 7;
                si[SI_STK + row * 8 + wsp] = 2 * pi + 2;
            }
            int sp1 = sp + (arity == 2 ? 1 : 0);
            int nxt, sp2;
            if (arity != 0) { nxt = 2 * pi + 1; sp2 = sp1; }
            else {
                int ridx = sp1 - 1; if (ridx < 0) ridx = 0; if (ridx > 7) ridx = 7;
                nxt = (sp1 > 0) ? si[SI_STK + row * 8 + ridx] : -1;
                sp2 = (sp1 > 0) ? sp1 - 1 : 0;
            }
            if (nxt > TT - 1) nxt = -1;
            if (nxt >= 0) {
                alive |= (1u << i);
                sm[S_LP + row]   = lpn;
                si[SI_POS + row] = nxt;
                si[SI_SP + row]  = sp2;
                si[SI_T + row]   = tt[i] + 1;
            } else {
                si[SI_ACT + row] = 0;
                out[OUT_LP + gr[i]] = lpn;
            }
        }
        // fold chosen token code into W_ih accumulator
        if (choice & 15) {
            int cb = 4 * pi;
#pragma unroll
            for (int m = 0; m < 4; m++) {
                int j = lane + 32 * m;
                float a = sm[S_ACC + row * HIDN + j];
#pragma unroll
                for (int b = 0; b < 4; b++)
                    if (choice & (1 << b))
                        a += __ldg(&g_WihT[(cb + b) * HIDN + j]);
                sm[S_ACC + row * HIDN + j] = a;
            }
        }
    }
    alive = __shfl_sync(FULLM, alive, 0);
    __syncwarp();
    return alive;
}

__device__ __forceinline__ unsigned run_old(int cnt, float* sm, int* si,
        const float* nt, const float* nc, float* out, const int* grp, int lane)
{
    switch (cnt) {
        case 4: return step_group<4, false>(sm, si, nt, nc, out, grp, lane);
        case 3: return step_group<3, false>(sm, si, nt, nc, out, grp, lane);
        case 2: return step_group<2, false>(sm, si, nt, nc, out, grp, lane);
        default: return step_group<1, false>(sm, si, nt, nc, out, grp, lane);
    }
}
__device__ __forceinline__ unsigned run_fresh(int cnt, float* sm, int* si,
        const float* nt, const float* nc, float* out, const int* grp, int lane)
{
    switch (cnt) {
        case 4: return step_group<4, true>(sm, si, nt, nc, out, grp, lane);
        case 3: return step_group<3, true>(sm, si, nt, nc, out, grp, lane);
        case 2: return step_group<2, true>(sm, si, nt, nc, out, grp, lane);
        default: return step_group<1, true>(sm, si, nt, nc, out, grp, lane);
    }
}

__global__ void __launch_bounds__(NTH, 1)
rnn_main(const float* __restrict__ x,
         const float* __restrict__ noise_tok,
         const float* __restrict__ noise_c,
         const float* __restrict__ W_ih,
         const float* __restrict__ W_hh,
         const float* __restrict__ b_ih,
         const float* __restrict__ b_hh,
         const float* __restrict__ W_out,
         const float* __restrict__ b_out,
         const float* __restrict__ W_c,
         const float* __restrict__ b_c,
         float* __restrict__ out)
{
    extern __shared__ float sm[];
    int* si = (int*)(sm + S_NF);
    int tid = threadIdx.x;
    int w = tid >> 5, lane = tid & 31;

    // ---- stage weights ----
    {   // W_hh k-quads: dst4[kq*128 + j] = {W_hh[j][4kq..4kq+3]}
        const float4* src = (const float4*)W_hh;   // [j][32]
        float4* dst = (float4*)(sm + S_WHH);
        for (int idx = tid; idx < 32 * 128; idx += NTH) {
            int kq = idx >> 7, j = idx & 127;
            dst[kq * 128 + j] = src[j * 32 + kq];
        }
    }
    {   // token head k-quads (zero-pad v 19..31)
        float4* dst = (float4*)(sm + S_TOKP);
        const float4 z4 = make_float4(0.f, 0.f, 0.f, 0.f);
        const float4* src = (const float4*)W_out;  // [v][32]
        for (int idx = tid; idx < 32 * 32; idx += NTH) {
            int kq = idx >> 5, v = idx & 31;
            dst[kq * 32 + v] = (v < NVOCAB) ? src[v * 32 + kq] : z4;
        }
    }
    for (int idx = tid; idx < HIDN * 64; idx += NTH) sm[S_CON + idx] = 0.f;
    __syncthreads();
    for (int idx = tid; idx < NCONST * HIDN; idx += NTH) {
        int c = idx / HIDN, k = idx % HIDN;
        sm[S_CON + k * 64 + c] = W_c[idx];
    }
    for (int idx = tid; idx < 9 * HIDN; idx += NTH) {
        int f = idx >> 7, j = idx & 127;
        sm[S_WX + f * 128 + j] = W_ih[j * INSZ + 124 + f];
    }
    if (tid < HIDN) sm[S_BSUM + tid] = b_ih[tid] + b_hh[tid];
    if (tid < 32) sm[S_BTOK + tid] = (tid < NVOCAB) ? b_out[tid] : 0.f;
    if (tid < 64) sm[S_BCON + tid] = (tid < NCONST) ? b_c[tid] : 0.f;
    if (tid < SLOTS) si[SI_ACT + tid] = 0;
    __syncthreads();

    // ---- persistent work loop ----
    for (;;) {
        if (w == 0) {
            int s0 = lane, s1 = 32 + lane;
            int f0 = si[SI_ACT + s0];
            int f1 = si[SI_ACT + s1];
            unsigned d0m = __ballot_sync(FULLM, !f0);
            unsigned d1m = __ballot_sync(FULLM, !f1);
            int nd0 = __popc(d0m);
            int nd = nd0 + __popc(d1m);
            int base = 0;
            if (lane == 0 && nd > 0) base = atomicAdd(&g_next, nd);
            base = __shfl_sync(FULLM, base, 0);
            int navail = BSZ - base;
            if (navail < 0) navail = 0;
            if (navail > nd) navail = nd;
            unsigned lt = (1u << lane) - 1u;
            int q0 = __popc(d0m & lt);
            int q1 = nd0 + __popc(d1m & lt);
            if (!f0) si[SI_DEAD + q0] = s0;
            if (!f1) si[SI_DEAD + q1] = s1;
            // survivors (old) first in LIST
            unsigned am0 = __ballot_sync(FULLM, f0 != 0);
            unsigned am1 = __ballot_sync(FULLM, f1 != 0);
            int c0 = __popc(am0);
            if (f0) si[SI_LIST + __popc(am0 & lt)] = s0;
            if (f1) si[SI_LIST + c0 + __popc(am1 & lt)] = s1;
            int oldc = c0 + __popc(am1);
            __syncwarp();
            // fresh appended after old
            for (int q = lane; q < navail; q += 32)
                si[SI_LIST + oldc + q] = si[SI_DEAD + q];
            if (lane == 0) {
                si[SI_CNT]     = oldc + navail;
                si[SI_CNT + 1] = navail;
                si[SI_CNT + 2] = base;
                si[SI_CNT + 3] = oldc;
            }
        }
        __syncthreads();
        int A = si[SI_CNT];
        int navail = si[SI_CNT + 1];
        int rbase  = si[SI_CNT + 2];
        int oldc   = si[SI_CNT + 3];
        if (A == 0) break;
        // pool drained? run surviving trees to completion in this round
        int subs = (si[SI_CNT + 2] + navail >= BSZ && navail == 0) ? TT : 2;
        if (rbase >= BSZ) subs = TT;

        // refill: init acc and h = tanh(acc)  (first-step GEMV is identically zero)
        for (int q = w; q < navail; q += 16) {
            int slot = si[SI_DEAD + q];
            int gr = rbase + q;
            float xv[9];
#pragma unroll
            for (int f = 0; f < 9; f++) xv[f] = __ldg(&x[gr * 9 + f]);
#pragma unroll
            for (int m = 0; m < 4; m++) {
                int j = lane + 32 * m;
                float a = sm[S_BSUM + j];
#pragma unroll
                for (int f = 0; f < 9; f++) a = fmaf(xv[f], sm[S_WX + f * 128 + j], a);
                sm[S_ACC + slot * HIDN + j] = a;
                sm[S_H + slot * HIDN + j] = tanhf(a);
            }
            if (lane == 0) {
                si[SI_POS + slot]  = 0;
                si[SI_ACT + slot]  = 1;
                si[SI_GROW + slot] = gr;
            }
        }
        __syncthreads();

        int sbase = 4 * w;
        if (sbase < A) {
            int e  = sbase + 4 < A ? sbase + 4 : A;
            int oe = e < oldc ? e : oldc;
            int no = oe - sbase;                  // old rows for this warp
            int agrp[4];
            int acnt = 0;
            if (no > 0) {
                int grp[4];
#pragma unroll
                for (int q = 0; q < 4; q++)
                    grp[q] = si[SI_LIST + sbase + (q < no ? q : 0)];
                unsigned mvk = run_old(no, sm, si, noise_tok, noise_c, out, grp, lane);
                for (int q = 0; q < no; q++)
                    if ((mvk >> q) & 1) agrp[acnt++] = grp[q];
            }
            int fb = sbase > oldc ? sbase : oldc;
            int nf = e - fb;                      // fresh rows for this warp
            if (nf > 0) {
                int grp[4];
#pragma unroll
                for (int q = 0; q < 4; q++)
                    grp[q] = si[SI_LIST + fb + (q < nf ? q : 0)];
                unsigned mvk = run_fresh(nf, sm, si, noise_tok, noise_c, out, grp, lane);
                for (int q = 0; q < nf; q++)
                    if ((mvk >> q) & 1) agrp[acnt++] = grp[q];
            }
            // extra substeps: per-row recurrence is warp-local
            for (int s = 1; s < subs && acnt > 0; s++) {
                int grp[4];
#pragma unroll
                for (int q = 0; q < 4; q++)
                    grp[q] = agrp[q < acnt ? q : 0];
                unsigned mvk = run_old(acnt, sm, si, noise_tok, noise_c, out, grp, lane);
                int nn = 0;
                for (int q = 0; q < acnt; q++)
                    if ((mvk >> q) & 1) agrp[nn++] = grp[q];
                acnt = nn;
            }
        }
        __syncthreads();
    }
}

// merged prep + output-init
__global__ void setup_kernel(const float* __restrict__ W_ih, float* __restrict__ out)
{
    int i = blockIdx.x * blockDim.x + threadIdx.x;
    if (i == 0) g_next = 0;
    if (i < INSZ * HIDN) {
        int c = i / HIDN, j = i % HIDN;
        g_WihT[c * HIDN + j] = W_ih[j * INSZ + c];
    }
    float4* o4 = (float4*)out;
    const int n4 = OUT_TOT / 4;
    int stride = gridDim.x * blockDim.x;
    for (int k = i; k < n4; k += stride) {
        float v = (k * 4 < OUT_CV) ? -1.f : 0.f;
        o4[k] = make_float4(v, v, v, v);
    }
}

extern "C" void kernel_launch(void* const* d_in, const int* in_sizes, int n_in,
                              void* d_out, int out_size)
{
    const float* x    = (const float*)d_in[0];
    const float* nt   = (const float*)d_in[1];
    const float* nc   = (const float*)d_in[2];
    const float* wih  = (const float*)d_in[3];
    const float* whh  = (const float*)d_in[4];
    const float* bih  = (const float*)d_in[5];
    const float* bhh  = (const float*)d_in[6];
    const float* wout = (const float*)d_in[7];
    const float* bout = (const float*)d_in[8];
    const float* wc   = (const float*)d_in[9];
    const float* bc   = (const float*)d_in[10];
    float* out = (float*)d_out;

    cudaFuncSetAttribute((const void*)rnn_main,
                         cudaFuncAttributeMaxDynamicSharedMemorySize, SMEM_BYTES);
    setup_kernel<<<512, 256>>>(wih, out);
    rnn_main<<<NBLK, NTH, SMEM_BYTES>>>(x, nt, nc, wih, whh, bih, bhh,
                                        wout, bout, wc, bc, out);
}

// round 8
// speedup vs baseline: 1.3251x; 1.3140x over previous
#include <cuda_runtime.h>
#include <math.h>

#define BSZ    65536
#define TT     31
#define HIDN   128
#define NVOCAB 19
#define NCONST 40
#define INSZ   133
#define SLOTS  64
#define NTH    512
#define NBLK   152

#define OUT_CV  2031616   // BSZ*TT
#define OUT_LP  4063232   // 2*BSZ*TT
#define OUT_TOT 4194304

typedef unsigned long long u64;

// shared float layout (identical to R5)
#define S_WHH  0            // float4[kq=32][j=128]
#define S_TOKP 16384        // float4[kq=32][v=32]
#define S_CON  20480        // [k][64]
#define S_H    28672        // [64][128]
#define S_ACC  36864        // [64][128]
#define S_WX   45056        // [f=9][j=128]
#define S_BSUM 46208
#define S_BTOK 46336
#define S_BCON 46368
#define S_LP   46432
#define S_NF   46496
// int region
#define SI_POS  0
#define SI_SP   64
#define SI_ACT  128
#define SI_T    192
#define SI_GROW 256
#define SI_STK  320         // 64 x 8
#define SI_N    832
#define SMEM_BYTES ((S_NF + SI_N) * 4)

#define FULLM 0xffffffffu

__device__ float g_WihT[INSZ * HIDN];   // [c][j]
__device__ int   g_next;

__device__ __forceinline__ u64 ffma2(u64 a, u64 b, u64 c) {
    u64 d;
    asm("fma.rn.f32x2 %0, %1, %2, %3;" : "=l"(d) : "l"(a), "l"(b), "l"(c));
    return d;
}
__device__ __forceinline__ float f2lo(u64 v) { return __uint_as_float((unsigned)v); }
__device__ __forceinline__ float f2hi(u64 v) { return __uint_as_float((unsigned)(v >> 32)); }

__device__ __forceinline__ void lds2(u64& a, u64& b, const float* p) {
    unsigned addr = (unsigned)__cvta_generic_to_shared(p);
    asm("ld.shared.v2.b64 {%0, %1}, [%2];" : "=l"(a), "=l"(b) : "r"(addr));
}

__device__ __forceinline__ float gumbelf(float u) {
    float inner = -logf(u + 1e-9f);
    return -logf(inner + 1e-9f);
}
__device__ __forceinline__ float wmaxf(float v) {
#pragma unroll
    for (int o = 16; o; o >>= 1) v = fmaxf(v, __shfl_xor_sync(FULLM, v, o));
    return v;
}
__device__ __forceinline__ float wsumf(float v) {
#pragma unroll
    for (int o = 16; o; o >>= 1) v += __shfl_xor_sync(FULLM, v, o);
    return v;
}
__device__ __forceinline__ void wargmax(float& s, int& i, float& lp) {
#pragma unroll
    for (int o = 16; o; o >>= 1) {
        float s2 = __shfl_xor_sync(FULLM, s, o);
        int   i2 = __shfl_xor_sync(FULLM, i, o);
        float l2 = __shfl_xor_sync(FULLM, lp, o);
        if (s2 > s || (s2 == s && i2 < i)) { s = s2; i = i2; lp = l2; }
    }
}

// GEMV + tanh + store h for CNT (non-fresh) rows — identical math to R5 Phase A
template<int CNT>
__device__ __forceinline__ void phaseA(float* sm, const int* grp, int lane)
{
    u64 zp[CNT][4];
#pragma unroll
    for (int i = 0; i < CNT; i++)
#pragma unroll
        for (int m = 0; m < 4; m++) zp[i][m] = 0ull;
#pragma unroll 4
    for (int kq = 0; kq < 32; kq++) {
        u64 h01[CNT], h23[CNT];
#pragma unroll
        for (int i = 0; i < CNT; i++)
            lds2(h01[i], h23[i], sm + S_H + grp[i] * HIDN + 4 * kq);
#pragma unroll
        for (int m = 0; m < 4; m++) {
            u64 w01, w23;
            lds2(w01, w23, sm + S_WHH + (kq * 128 + lane + 32 * m) * 4);
#pragma unroll
            for (int i = 0; i < CNT; i++) {
                zp[i][m] = ffma2(h01[i], w01, zp[i][m]);
                zp[i][m] = ffma2(h23[i], w23, zp[i][m]);
            }
        }
    }
    float hnew[CNT][4];
#pragma unroll
    for (int i = 0; i < CNT; i++)
#pragma unroll
        for (int m = 0; m < 4; m++) {
            int j = lane + 32 * m;
            float z = f2lo(zp[i][m]) + f2hi(zp[i][m]);
            float a = sm[S_ACC + grp[i] * HIDN + j];
            hnew[i][m] = tanhf(z + a);
        }
    __syncwarp();
#pragma unroll
    for (int i = 0; i < CNT; i++)
#pragma unroll
        for (int m = 0; m < 4; m++)
            sm[S_H + grp[i] * HIDN + lane + 32 * m] = hnew[i][m];
    __syncwarp();
}

// head + sampling + bookkeeping for CNT rows (fresh & old alike; t/pos/sp from si)
template<int CNT>
__device__ __forceinline__ void phaseBC(float* sm, int* si,
                           const float* __restrict__ noise_c,
                           float* __restrict__ out,
                           const int* grp, const int* p, const int* tt,
                           const int* gr, const float* g_t, int lane)
{
    // Phase B: token head logits (lane = vocab index)
    u64 tkp[CNT];
#pragma unroll
    for (int i = 0; i < CNT; i++) tkp[i] = 0ull;
#pragma unroll 4
    for (int kq = 0; kq < 32; kq++) {
        u64 w01, w23;
        lds2(w01, w23, sm + S_TOKP + (kq * 32 + lane) * 4);
#pragma unroll
        for (int i = 0; i < CNT; i++) {
            u64 h01, h23;
            lds2(h01, h23, sm + S_H + grp[i] * HIDN + 4 * kq);
            tkp[i] = ffma2(h01, w01, tkp[i]);
            tkp[i] = ffma2(h23, w23, tkp[i]);
        }
    }
    float btok = sm[S_BTOK + lane];
    const float NEGINF = -INFINITY;

    // Phase C1: batched softmax + Gumbel argmax
    float ltok[CNT];
#pragma unroll
    for (int i = 0; i < CNT; i++) {
        float l = NEGINF;
        if (lane < NVOCAB) {
            l = f2lo(tkp[i]) + f2hi(tkp[i]) + btok;
            if (p[i] >= 15 && lane < 6) l = NEGINF;
        }
        ltok[i] = l;
    }
    float mx[CNT];
#pragma unroll
    for (int i = 0; i < CNT; i++) mx[i] = ltok[i];
#pragma unroll
    for (int o = 16; o; o >>= 1)
#pragma unroll
        for (int i = 0; i < CNT; i++)
            mx[i] = fmaxf(mx[i], __shfl_xor_sync(FULLM, mx[i], o));
    float sme[CNT];
#pragma unroll
    for (int i = 0; i < CNT; i++)
        sme[i] = (lane < NVOCAB) ? expf(ltok[i] - mx[i]) : 0.f;
#pragma unroll
    for (int o = 16; o; o >>= 1)
#pragma unroll
        for (int i = 0; i < CNT; i++)
            sme[i] += __shfl_xor_sync(FULLM, sme[i], o);
    float sc[CNT], lpw[CNT];
    int ci[CNT];
#pragma unroll
    for (int i = 0; i < CNT; i++) {
        float lse = logf(sme[i]);
        float lpt = ltok[i] - mx[i] - lse;
        sc[i]  = lpt + g_t[i];
        ci[i]  = lane;
        lpw[i] = lpt;
    }
#pragma unroll
    for (int o = 16; o; o >>= 1) {
#pragma unroll
        for (int i = 0; i < CNT; i++) {
            float s2 = __shfl_xor_sync(FULLM, sc[i], o);
            int   i2 = __shfl_xor_sync(FULLM, ci[i], o);
            float l2 = __shfl_xor_sync(FULLM, lpw[i], o);
            if (s2 > sc[i] || (s2 == sc[i] && i2 < ci[i])) {
                sc[i] = s2; ci[i] = i2; lpw[i] = l2;
            }
        }
    }

    // Phase C2: rare const head + bookkeeping
#pragma unroll
    for (int i = 0; i < CNT; i++) {
        int row = grp[i];
        int pi  = p[i];
        int choice = ci[i];
        float lp_tok = lpw[i];

        bool is_const = (choice == 18);
        float lp_c = 0.f; int cchoice = 0;
        if (is_const) {   // warp-uniform
            float2 co = make_float2(0.f, 0.f);
#pragma unroll 8
            for (int k4 = 0; k4 < 32; k4++) {
                float4 hv = *(const float4*)(sm + S_H + row * HIDN + 4 * k4);
#pragma unroll
                for (int b = 0; b < 4; b++) {
                    float2 wc = *(const float2*)(sm + S_CON + (4 * k4 + b) * 64 + 2 * lane);
                    float hk = (b == 0) ? hv.x : (b == 1) ? hv.y : (b == 2) ? hv.z : hv.w;
                    co.x = fmaf(hk, wc.x, co.x);
                    co.y = fmaf(hk, wc.y, co.y);
                }
            }
            long long bt = (long long)tt[i] * BSZ + gr[i];
            float2 uc = make_float2(0.f, 0.f);
            if (lane < 20) uc = *(const float2*)(&noise_c[bt * NCONST + 2 * lane]);
            float bc0 = sm[S_BCON + 2 * lane];
            float bc1 = sm[S_BCON + 2 * lane + 1];
            float la = (lane < 20) ? (co.x + bc0) : NEGINF;
            float lb = (lane < 20) ? (co.y + bc1) : NEGINF;
            float mc   = wmaxf(fmaxf(la, lb));
            float ec   = (lane < 20) ? (expf(la - mc) + expf(lb - mc)) : 0.f;
            float lsec = logf(wsumf(ec));
            float lpa = la - mc - lsec;
            float lpb = lb - mc - lsec;
            float sa = lpa + gumbelf(uc.x);
            float sb = lpb + gumbelf(uc.y);
            float s_l, lp_l; int i_l;
            if (sb > sa) { s_l = sb; i_l = 2 * lane + 1; lp_l = lpb; }
            else         { s_l = sa; i_l = 2 * lane;     lp_l = lpa; }
            wargmax(s_l, i_l, lp_l);
            cchoice = i_l; lp_c = lp_l;
        }

        if (lane == 0) {
            float lpn = sm[S_LP + row] + lp_tok + (is_const ? lp_c : 0.f);
            out[gr[i] * TT + pi] = (float)choice;
            if (is_const) out[OUT_CV + gr[i] * TT + pi] = -10.f + 0.5f * (float)cchoice;
            int arity = (choice < 4) ? 2 : ((choice < 6) ? 1 : 0);
            int sp = si[SI_SP + row];
            if (arity == 2) {
                int wsp = sp < 7 ? sp : 7;
                si[SI_STK + row * 8 + wsp] = 2 * pi + 2;
            }
            int sp1 = sp + (arity == 2 ? 1 : 0);
            int nxt, sp2;
            if (arity != 0) { nxt = 2 * pi + 1; sp2 = sp1; }
            else {
                int ridx = sp1 - 1; if (ridx < 0) ridx = 0; if (ridx > 7) ridx = 7;
                nxt = (sp1 > 0) ? si[SI_STK + row * 8 + ridx] : -1;
                sp2 = (sp1 > 0) ? sp1 - 1 : 0;
            }
            if (nxt > TT - 1) nxt = -1;
            if (nxt >= 0) {
                sm[S_LP + row]   = lpn;
                si[SI_POS + row] = nxt;
                si[SI_SP + row]  = sp2;
                si[SI_T + row]   = tt[i] + 1;
            } else {
                si[SI_ACT + row] = 0;
                out[OUT_LP + gr[i]] = lpn;
            }
        }
        // fold chosen token code into W_ih accumulator
        if (choice & 15) {
            int cb = 4 * pi;
#pragma unroll
            for (int m = 0; m < 4; m++) {
                int j = lane + 32 * m;
                float a = sm[S_ACC + row * HIDN + j];
#pragma unroll
                for (int b = 0; b < 4; b++)
                    if (choice & (1 << b))
                        a += __ldg(&g_WihT[(cb + b) * HIDN + j]);
                sm[S_ACC + row * HIDN + j] = a;
            }
        }
    }
}

__global__ void __launch_bounds__(NTH, 1)
rnn_main(const float* __restrict__ x,
         const float* __restrict__ noise_tok,
         const float* __restrict__ noise_c,
         const float* __restrict__ W_ih,
         const float* __restrict__ W_hh,
         const float* __restrict__ b_ih,
         const float* __restrict__ b_hh,
         const float* __restrict__ W_out,
         const float* __restrict__ b_out,
         const float* __restrict__ W_c,
         const float* __restrict__ b_c,
         float* __restrict__ out)
{
    extern __shared__ float sm[];
    int* si = (int*)(sm + S_NF);
    int tid = threadIdx.x;
    int w = tid >> 5, lane = tid & 31;
    int w4 = w * 4;

    // ---- stage weights (same as R5) ----
    {
        const float4* src = (const float4*)W_hh;   // [j][32]
        float4* dst = (float4*)(sm + S_WHH);
        for (int idx = tid; idx < 32 * 128; idx += NTH) {
            int kq = idx >> 7, j = idx & 127;
            dst[kq * 128 + j] = src[j * 32 + kq];
        }
    }
    {
        float4* dst = (float4*)(sm + S_TOKP);
        const float4 z4 = make_float4(0.f, 0.f, 0.f, 0.f);
        const float4* src = (const float4*)W_out;  // [v][32]
        for (int idx = tid; idx < 32 * 32; idx += NTH) {
            int kq = idx >> 5, v = idx & 31;
            dst[kq * 32 + v] = (v < NVOCAB) ? src[v * 32 + kq] : z4;
        }
    }
    for (int idx = tid; idx < HIDN * 64; idx += NTH) sm[S_CON + idx] = 0.f;
    __syncthreads();
    for (int idx = tid; idx < NCONST * HIDN; idx += NTH) {
        int c = idx / HIDN, k = idx % HIDN;
        sm[S_CON + k * 64 + c] = W_c[idx];
    }
    for (int idx = tid; idx < 9 * HIDN; idx += NTH) {
        int f = idx >> 7, j = idx & 127;
        sm[S_WX + f * 128 + j] = W_ih[j * INSZ + 124 + f];
    }
    if (tid < HIDN) sm[S_BSUM + tid] = b_ih[tid] + b_hh[tid];
    if (tid < 32) sm[S_BTOK + tid] = (tid < NVOCAB) ? b_out[tid] : 0.f;
    if (tid < 64) sm[S_BCON + tid] = (tid < NCONST) ? b_c[tid] : 0.f;
    if (tid < SLOTS) si[SI_ACT + tid] = 0;
    __syncthreads();

    // ---- warp-autonomous persistent loop: NO block barriers below ----
    bool pool_open = true;
    unsigned freshm = 0;

    for (;;) {
        // read own slots' activity
        int act[4];
#pragma unroll
        for (int q = 0; q < 4; q++) act[q] = si[SI_ACT + w4 + q];
        int deadm = 0;
#pragma unroll
        for (int q = 0; q < 4; q++) if (!act[q]) deadm |= (1 << q);
        int nd = __popc(deadm);
        freshm = 0;

        if (nd > 0 && pool_open) {
            int base = 0;
            if (lane == 0) base = atomicAdd(&g_next, nd);
            base = __shfl_sync(FULLM, base, 0);
            int avail = BSZ - base;
            if (avail < 0) avail = 0;
            if (avail > nd) avail = nd;
            if (avail < nd) pool_open = false;
            int got = 0;
#pragma unroll
            for (int q = 0; q < 4; q++) {
                if ((deadm >> q) & 1) {
                    if (got < avail) {
                        int slot = w4 + q;
                        int gr = base + got;
                        float xv[9];
#pragma unroll
                        for (int f = 0; f < 9; f++) xv[f] = __ldg(&x[gr * 9 + f]);
#pragma unroll
                        for (int m = 0; m < 4; m++) {
                            int j = lane + 32 * m;
                            float a = sm[S_BSUM + j];
#pragma unroll
                            for (int f = 0; f < 9; f++)
                                a = fmaf(xv[f], sm[S_WX + f * 128 + j], a);
                            sm[S_ACC + slot * HIDN + j] = a;
                            sm[S_H + slot * HIDN + j] = tanhf(a);  // step-0 h
                        }
                        if (lane == 0) {
                            si[SI_POS + slot]  = 0;
                            si[SI_SP + slot]   = 0;
                            si[SI_T + slot]    = 0;
                            si[SI_GROW + slot] = gr;
                            si[SI_ACT + slot]  = 1;
                            sm[S_LP + slot]    = 0.f;
                        }
                        act[q] = 1;
                        freshm |= (1u << q);
                        got++;
                    }
                }
            }
            __syncwarp();
        }

        // gather active slots: old (need GEMV) first, fresh after
        int grp[4];
        int nact = 0;
#pragma unroll
        for (int q = 0; q < 4; q++)
            if (act[q] && !((freshm >> q) & 1)) grp[nact++] = w4 + q;
        int nold = nact;
#pragma unroll
        for (int q = 0; q < 4; q++)
            if (act[q] && ((freshm >> q) & 1)) grp[nact++] = w4 + q;
        if (nact == 0) break;   // warp done

        // per-row scalars + noise prefetch (gumbel logf overlaps GEMV)
        int p[4], tt[4], gr[4];
        float g_t[4];
#pragma unroll
        for (int i = 0; i < 4; i++) {
            if (i < nact) {
                int row = grp[i];
                p[i]  = si[SI_POS + row];
                tt[i] = si[SI_T + row];
                gr[i] = si[SI_GROW + row];
                long long bt = (long long)tt[i] * BSZ + gr[i];
                float u = (lane < NVOCAB) ? __ldg(&noise_tok[bt * NVOCAB + lane]) : 0.5f;
                g_t[i] = gumbelf(u);
            }
        }

        switch (nold) {
            case 4: phaseA<4>(sm, grp, lane); break;
            case 3: phaseA<3>(sm, grp, lane); break;
            case 2: phaseA<2>(sm, grp, lane); break;
            case 1: phaseA<1>(sm, grp, lane); break;
            default: break;
        }
        switch (nact) {
            case 4: phaseBC<4>(sm, si, noise_c, out, grp, p, tt, gr, g_t, lane); break;
            case 3: phaseBC<3>(sm, si, noise_c, out, grp, p, tt, gr, g_t, lane); break;
            case 2: phaseBC<2>(sm, si, noise_c, out, grp, p, tt, gr, g_t, lane); break;
            default: phaseBC<1>(sm, si, noise_c, out, grp, p, tt, gr, g_t, lane); break;
        }
        __syncwarp();
    }
}

// merged prep + output-init
__global__ void setup_kernel(const float* __restrict__ W_ih, float* __restrict__ out)
{
    int i = blockIdx.x * blockDim.x + threadIdx.x;
    if (i == 0) g_next = 0;
    if (i < INSZ * HIDN) {
        int c = i / HIDN, j = i % HIDN;
        g_WihT[c * HIDN + j] = W_ih[j * INSZ + c];
    }
    float4* o4 = (float4*)out;
    const int n4 = OUT_TOT / 4;
    int stride = gridDim.x * blockDim.x;
    for (int k = i; k < n4; k += stride) {
        float v = (k * 4 < OUT_CV) ? -1.f : 0.f;
        o4[k] = make_float4(v, v, v, v);
    }
}

extern "C" void kernel_launch(void* const* d_in, const int* in_sizes, int n_in,
                              void* d_out, int out_size)
{
    const float* x    = (const float*)d_in[0];
    const float* nt   = (const float*)d_in[1];
    const float* nc   = (const float*)d_in[2];
    const float* wih  = (const float*)d_in[3];
    const float* whh  = (const float*)d_in[4];
    const float* bih  = (const float*)d_in[5];
    const float* bhh  = (const float*)d_in[6];
    const float* wout = (const float*)d_in[7];
    const float* bout = (const float*)d_in[8];
    const float* wc   = (const float*)d_in[9];
    const float* bc   = (const float*)d_in[10];
    float* out = (float*)d_out;

    cudaFuncSetAttribute((const void*)rnn_main,
                         cudaFuncAttributeMaxDynamicSharedMemorySize, SMEM_BYTES);
    setup_kernel<<<512, 256>>>(wih, out);
    rnn_main<<<NBLK, NTH, SMEM_BYTES>>>(x, nt, nc, wih, whh, bih, bhh,
                                        wout, bout, wc, bc, out);
}

// round 9
// speedup vs baseline: 1.5077x; 1.1378x over previous
#include <cuda_runtime.h>
#include <math.h>

#define BSZ    65536
#define TT     31
#define HIDN   128
#define NVOCAB 19
#define NCONST 40
#define INSZ   133
#define SLOTS  96
#define NTH    512
#define NBLK   152

#define OUT_CV  2031616   // BSZ*TT
#define OUT_LP  4063232   // 2*BSZ*TT
#define OUT_TOT 4194304

typedef unsigned long long u64;

// shared float layout
#define S_WHH  0            // float4[kq=32][j=128]
#define S_TOKP 16384        // float4[kq=32][v=32]
#define S_CON  20480        // [k][64]
#define S_H    28672        // [96][128]
#define S_ACC  40960        // [96][128]
#define S_WX   53248        // [f=9][j=128]
#define S_BSUM 54400
#define S_BTOK 54528
#define S_BCON 54560
#define S_LP   54624        // 96
#define S_NF   54720
// int region
#define SI_POS  0
#define SI_SP   96
#define SI_ACT  192
#define SI_T    288
#define SI_GROW 384
#define SI_STK  480         // 96 x 8
#define SI_LIST 1248        // 96
#define SI_DEAD 1344        // 96
#define SI_CNT  1440        // [0]=A [1]=navail [2]=base [3]=oldc
#define SI_N    1444
#define SMEM_BYTES ((S_NF + SI_N) * 4)

#define FULLM 0xffffffffu

__device__ float g_WihT[INSZ * HIDN];   // [c][j]
__device__ int   g_next;

__device__ __forceinline__ u64 ffma2(u64 a, u64 b, u64 c) {
    u64 d;
    asm("fma.rn.f32x2 %0, %1, %2, %3;" : "=l"(d) : "l"(a), "l"(b), "l"(c));
    return d;
}
__device__ __forceinline__ float f2lo(u64 v) { return __uint_as_float((unsigned)v); }
__device__ __forceinline__ float f2hi(u64 v) { return __uint_as_float((unsigned)(v >> 32)); }

__device__ __forceinline__ void lds2(u64& a, u64& b, const float* p) {
    unsigned addr = (unsigned)__cvta_generic_to_shared(p);
    asm("ld.shared.v2.b64 {%0, %1}, [%2];" : "=l"(a), "=l"(b) : "r"(addr));
}

__device__ __forceinline__ float gumbelf(float u) {
    float inner = -logf(u + 1e-9f);
    return -logf(inner + 1e-9f);
}
__device__ __forceinline__ float wmaxf(float v) {
#pragma unroll
    for (int o = 16; o; o >>= 1) v = fmaxf(v, __shfl_xor_sync(FULLM, v, o));
    return v;
}
__device__ __forceinline__ float wsumf(float v) {
#pragma unroll
    for (int o = 16; o; o >>= 1) v += __shfl_xor_sync(FULLM, v, o);
    return v;
}
__device__ __forceinline__ void wargmax(float& s, int& i, float& lp) {
#pragma unroll
    for (int o = 16; o; o >>= 1) {
        float s2 = __shfl_xor_sync(FULLM, s, o);
        int   i2 = __shfl_xor_sync(FULLM, i, o);
        float l2 = __shfl_xor_sync(FULLM, lp, o);
        if (s2 > s || (s2 == s && i2 < i)) { s = s2; i = i2; lp = l2; }
    }
}

// One decode step for CNT rows; returns survivor bitmask (bit i set iff grp[i]
// is still active afterwards), broadcast to all lanes. Math identical to R5.
template<int CNT, bool FRESH>
__device__ __forceinline__ unsigned step_group(float* sm, int* si,
                           const float* __restrict__ noise_tok,
                           const float* __restrict__ noise_c,
                           float* __restrict__ out,
                           const int* grp, int lane)
{
    int p[CNT], tt[CNT], gr[CNT];
    float g_t[CNT];
#pragma unroll
    for (int i = 0; i < CNT; i++) {
        int row = grp[i];
        p[i]  = FRESH ? 0 : si[SI_POS + row];
        tt[i] = FRESH ? 0 : si[SI_T + row];
        gr[i] = si[SI_GROW + row];
        long long bt = (long long)tt[i] * BSZ + gr[i];
        float u = (lane < NVOCAB) ? __ldg(&noise_tok[bt * NVOCAB + lane]) : 0.5f;
        g_t[i] = gumbelf(u);   // overlaps GEMV below
    }

    if (!FRESH) {
        // Phase A: z = W_hh * h ; lane owns j = lane + 32m ; k-quad vectorized
        u64 zp[CNT][4];
#pragma unroll
        for (int i = 0; i < CNT; i++)
#pragma unroll
            for (int m = 0; m < 4; m++) zp[i][m] = 0ull;
#pragma unroll 4
        for (int kq = 0; kq < 32; kq++) {
            u64 h01[CNT], h23[CNT];
#pragma unroll
            for (int i = 0; i < CNT; i++)
                lds2(h01[i], h23[i], sm + S_H + grp[i] * HIDN + 4 * kq);
#pragma unroll
            for (int m = 0; m < 4; m++) {
                u64 w01, w23;
                lds2(w01, w23, sm + S_WHH + (kq * 128 + lane + 32 * m) * 4);
#pragma unroll
                for (int i = 0; i < CNT; i++) {
                    zp[i][m] = ffma2(h01[i], w01, zp[i][m]);
                    zp[i][m] = ffma2(h23[i], w23, zp[i][m]);
                }
            }
        }
        float hnew[CNT][4];
#pragma unroll
        for (int i = 0; i < CNT; i++)
#pragma unroll
            for (int m = 0; m < 4; m++) {
                int j = lane + 32 * m;
                float z = f2lo(zp[i][m]) + f2hi(zp[i][m]);
                float a = sm[S_ACC + grp[i] * HIDN + j];
                hnew[i][m] = tanhf(z + a);
            }
        __syncwarp();
#pragma unroll
        for (int i = 0; i < CNT; i++)
#pragma unroll
            for (int m = 0; m < 4; m++)
                sm[S_H + grp[i] * HIDN + lane + 32 * m] = hnew[i][m];
        __syncwarp();
    }

    // Phase B: token head logits (lane = vocab index)
    u64 tkp[CNT];
#pragma unroll
    for (int i = 0; i < CNT; i++) tkp[i] = 0ull;
#pragma unroll 4
    for (int kq = 0; kq < 32; kq++) {
        u64 w01, w23;
        lds2(w01, w23, sm + S_TOKP + (kq * 32 + lane) * 4);
#pragma unroll
        for (int i = 0; i < CNT; i++) {
            u64 h01, h23;
            lds2(h01, h23, sm + S_H + grp[i] * HIDN + 4 * kq);
            tkp[i] = ffma2(h01, w01, tkp[i]);
            tkp[i] = ffma2(h23, w23, tkp[i]);
        }
    }
    float btok = sm[S_BTOK + lane];
    const float NEGINF = -INFINITY;

    // Phase C1: batched softmax + Gumbel argmax
    float ltok[CNT];
#pragma unroll
    for (int i = 0; i < CNT; i++) {
        float l = NEGINF;
        if (lane < NVOCAB) {
            l = f2lo(tkp[i]) + f2hi(tkp[i]) + btok;
            if (p[i] >= 15 && lane < 6) l = NEGINF;
        }
        ltok[i] = l;
    }
    float mx[CNT];
#pragma unroll
    for (int i = 0; i < CNT; i++) mx[i] = ltok[i];
#pragma unroll
    for (int o = 16; o; o >>= 1)
#pragma unroll
        for (int i = 0; i < CNT; i++)
            mx[i] = fmaxf(mx[i], __shfl_xor_sync(FULLM, mx[i], o));
    float sme[CNT];
#pragma unroll
    for (int i = 0; i < CNT; i++)
        sme[i] = (lane < NVOCAB) ? expf(ltok[i] - mx[i]) : 0.f;
#pragma unroll
    for (int o = 16; o; o >>= 1)
#pragma unroll
        for (int i = 0; i < CNT; i++)
            sme[i] += __shfl_xor_sync(FULLM, sme[i], o);
    float sc[CNT], lpw[CNT];
    int ci[CNT];
#pragma unroll
    for (int i = 0; i < CNT; i++) {
        float lse = logf(sme[i]);
        float lpt = ltok[i] - mx[i] - lse;
        sc[i]  = lpt + g_t[i];
        ci[i]  = lane;
        lpw[i] = lpt;
    }
#pragma unroll
    for (int o = 16; o; o >>= 1) {
#pragma unroll
        for (int i = 0; i < CNT; i++) {
            float s2 = __shfl_xor_sync(FULLM, sc[i], o);
            int   i2 = __shfl_xor_sync(FULLM, ci[i], o);
            float l2 = __shfl_xor_sync(FULLM, lpw[i], o);
            if (s2 > sc[i] || (s2 == sc[i] && i2 < ci[i])) {
                sc[i] = s2; ci[i] = i2; lpw[i] = l2;
            }
        }
    }

    // Phase C2: rare const head + bookkeeping
    unsigned alive = 0;
#pragma unroll
    for (int i = 0; i < CNT; i++) {
        int row = grp[i];
        int pi  = p[i];
        int choice = ci[i];
        float lp_tok = lpw[i];

        bool is_const = (choice == 18);
        float lp_c = 0.f; int cchoice = 0;
        if (is_const) {   // warp-uniform
            float2 co = make_float2(0.f, 0.f);
#pragma unroll 8
            for (int k4 = 0; k4 < 32; k4++) {
                float4 hv = *(const float4*)(sm + S_H + row * HIDN + 4 * k4);
#pragma unroll
                for (int b = 0; b < 4; b++) {
                    float2 wc = *(const float2*)(sm + S_CON + (4 * k4 + b) * 64 + 2 * lane);
                    float hk = (b == 0) ? hv.x : (b == 1) ? hv.y : (b == 2) ? hv.z : hv.w;
                    co.x = fmaf(hk, wc.x, co.x);
                    co.y = fmaf(hk, wc.y, co.y);
                }
            }
            long long bt = (long long)tt[i] * BSZ + gr[i];
            float2 uc = make_float2(0.f, 0.f);
            if (lane < 20) uc = *(const float2*)(&noise_c[bt * NCONST + 2 * lane]);
            float bc0 = sm[S_BCON + 2 * lane];
            float bc1 = sm[S_BCON + 2 * lane + 1];
            float la = (lane < 20) ? (co.x + bc0) : NEGINF;
            float lb = (lane < 20) ? (co.y + bc1) : NEGINF;
            float mc   = wmaxf(fmaxf(la, lb));
            float ec   = (lane < 20) ? (expf(la - mc) + expf(lb - mc)) : 0.f;
            float lsec = logf(wsumf(ec));
            float lpa = la - mc - lsec;
            float lpb = lb - mc - lsec;
            float sa = lpa + gumbelf(uc.x);
            float sb = lpb + gumbelf(uc.y);
            float s_l, lp_l; int i_l;
            if (sb > sa) { s_l = sb; i_l = 2 * lane + 1; lp_l = lpb; }
            else         { s_l = sa; i_l = 2 * lane;     lp_l = lpa; }
            wargmax(s_l, i_l, lp_l);
            cchoice = i_l; lp_c = lp_l;
        }

        if (lane == 0) {
            float lpn = (FRESH ? 0.f : sm[S_LP + row]) + lp_tok + (is_const ? lp_c : 0.f);
            out[gr[i] * TT + pi] = (float)choice;
            if (is_const) out[OUT_CV + gr[i] * TT + pi] = -10.f + 0.5f * (float)cchoice;
            int arity = (choice < 4) ? 2 : ((choice < 6) ? 1 : 0);
            int sp = FRESH ? 0 : si[SI_SP + row];
            if (arity == 2) {
                int wsp = sp < 7 ? sp : 7;
                si[SI_STK + row * 8 + wsp] = 2 * pi + 2;
            }
            int sp1 = sp + (arity == 2 ? 1 : 0);
            int nxt, sp2;
            if (arity != 0) { nxt = 2 * pi + 1; sp2 = sp1; }
            else {
                int ridx = sp1 - 1; if (ridx < 0) ridx = 0; if (ridx > 7) ridx = 7;
                nxt = (sp1 > 0) ? si[SI_STK + row * 8 + ridx] : -1;
                sp2 = (sp1 > 0) ? sp1 - 1 : 0;
            }
            if (nxt > TT - 1) nxt = -1;
            if (nxt >= 0) {
                alive |= (1u << i);
                sm[S_LP + row]   = lpn;
                si[SI_POS + row] = nxt;
                si[SI_SP + row]  = sp2;
                si[SI_T + row]   = tt[i] + 1;
            } else {
                si[SI_ACT + row] = 0;
                out[OUT_LP + gr[i]] = lpn;
            }
        }
        if (choice & 15) {
            int cb = 4 * pi;
#pragma unroll
            for (int m = 0; m < 4; m++) {
                int j = lane + 32 * m;
                float a = sm[S_ACC + row * HIDN + j];
#pragma unroll
                for (int b = 0; b < 4; b++)
                    if (choice & (1 << b))
                        a += __ldg(&g_WihT[(cb + b) * HIDN + j]);
                sm[S_ACC + row * HIDN + j] = a;
            }
        }
    }
    alive = __shfl_sync(FULLM, alive, 0);
    __syncwarp();
    return alive;
}

__device__ __forceinline__ unsigned run_old(int cnt, float* sm, int* si,
        const float* nt, const float* nc, float* out, const int* grp, int lane)
{
    switch (cnt) {
        case 4: return step_group<4, false>(sm, si, nt, nc, out, grp, lane);
        case 3: return step_group<3, false>(sm, si, nt, nc, out, grp, lane);
        case 2: return step_group<2, false>(sm, si, nt, nc, out, grp, lane);
        default: return step_group<1, false>(sm, si, nt, nc, out, grp, lane);
    }
}
__device__ __forceinline__ unsigned run_fresh(int cnt, float* sm, int* si,
        const float* nt, const float* nc, float* out, const int* grp, int lane)
{
    switch (cnt) {
        case 4: return step_group<4, true>(sm, si, nt, nc, out, grp, lane);
        case 3: return step_group<3, true>(sm, si, nt, nc, out, grp, lane);
        case 2: return step_group<2, true>(sm, si, nt, nc, out, grp, lane);
        default: return step_group<1, true>(sm, si, nt, nc, out, grp, lane);
    }
}

__global__ void __launch_bounds__(NTH, 1)
rnn_main(const float* __restrict__ x,
         const float* __restrict__ noise_tok,
         const float* __restrict__ noise_c,
         const float* __restrict__ W_ih,
         const float* __restrict__ W_hh,
         const float* __restrict__ b_ih,
         const float* __restrict__ b_hh,
         const float* __restrict__ W_out,
         const float* __restrict__ b_out,
         const float* __restrict__ W_c,
         const float* __restrict__ b_c,
         float* __restrict__ out)
{
    extern __shared__ float sm[];
    int* si = (int*)(sm + S_NF);
    int tid = threadIdx.x;
    int w = tid >> 5, lane = tid & 31;

    // ---- stage weights ----
    {
        const float4* src = (const float4*)W_hh;   // [j][32]
        float4* dst = (float4*)(sm + S_WHH);
        for (int idx = tid; idx < 32 * 128; idx += NTH) {
            int kq = idx >> 7, j = idx & 127;
            dst[kq * 128 + j] = src[j * 32 + kq];
        }
    }
    {
        float4* dst = (float4*)(sm + S_TOKP);
        const float4 z4 = make_float4(0.f, 0.f, 0.f, 0.f);
        const float4* src = (const float4*)W_out;  // [v][32]
        for (int idx = tid; idx < 32 * 32; idx += NTH) {
            int kq = idx >> 5, v = idx & 31;
            dst[kq * 32 + v] = (v < NVOCAB) ? src[v * 32 + kq] : z4;
        }
    }
    for (int idx = tid; idx < HIDN * 64; idx += NTH) sm[S_CON + idx] = 0.f;
    __syncthreads();
    for (int idx = tid; idx < NCONST * HIDN; idx += NTH) {
        int c = idx / HIDN, k = idx % HIDN;
        sm[S_CON + k * 64 + c] = W_c[idx];
    }
    for (int idx = tid; idx < 9 * HIDN; idx += NTH) {
        int f = idx >> 7, j = idx & 127;
        sm[S_WX + f * 128 + j] = W_ih[j * INSZ + 124 + f];
    }
    if (tid < HIDN) sm[S_BSUM + tid] = b_ih[tid] + b_hh[tid];
    if (tid < 32) sm[S_BTOK + tid] = (tid < NVOCAB) ? b_out[tid] : 0.f;
    if (tid < 64) sm[S_BCON + tid] = (tid < NCONST) ? b_c[tid] : 0.f;
    if (tid < SLOTS) si[SI_ACT + tid] = 0;
    __syncthreads();

    // ---- persistent work loop ----
    for (;;) {
        if (w == 0) {
            unsigned lt = (1u << lane) - 1u;
            int nold = 0, ndead = 0;
            unsigned am[3];
            int po[3], pd[3];
#pragma unroll
            for (int c = 0; c < 3; c++) {
                int act = si[SI_ACT + 32 * c + lane];
                unsigned m = __ballot_sync(FULLM, act != 0);
                am[c] = m; po[c] = nold; pd[c] = ndead;
                nold  += __popc(m);
                ndead += 32 - __popc(m);
            }
            int base = 0;
            if (lane == 0 && ndead > 0) base = atomicAdd(&g_next, ndead);
            base = __shfl_sync(FULLM, base, 0);
            int navail = BSZ - base;
            if (navail < 0) navail = 0;
            if (navail > ndead) navail = ndead;
#pragma unroll
            for (int c = 0; c < 3; c++) {
                int slot = 32 * c + lane;
                if ((am[c] >> lane) & 1) si[SI_LIST + po[c] + __popc(am[c] & lt)] = slot;
                else                     si[SI_DEAD + pd[c] + __popc(~am[c] & lt)] = slot;
            }
            __syncwarp();
            for (int q = lane; q < navail; q += 32)
                si[SI_LIST + nold + q] = si[SI_DEAD + q];
            if (lane == 0) {
                si[SI_CNT]     = nold + navail;
                si[SI_CNT + 1] = navail;
                si[SI_CNT + 2] = (ndead > 0) ? base : 0;
                si[SI_CNT + 3] = nold;
            }
        }
        __syncthreads();
        int A = si[SI_CNT];
        int navail = si[SI_CNT + 1];
        int rbase  = si[SI_CNT + 2];
        int oldc   = si[SI_CNT + 3];
        if (A == 0) break;
        bool drain = (navail == 0) && (rbase >= BSZ);   // pool empty forever

        // refill: init acc and h = tanh(acc)  (first-step GEMV is identically zero)
        for (int q = w; q < navail; q += 16) {
            int slot = si[SI_DEAD + q];
            int gr = rbase + q;
            float xv[9];
#pragma unroll
            for (int f = 0; f < 9; f++) xv[f] = __ldg(&x[gr * 9 + f]);
#pragma unroll
            for (int m = 0; m < 4; m++) {
                int j = lane + 32 * m;
                float a = sm[S_BSUM + j];
#pragma unroll
                for (int f = 0; f < 9; f++) a = fmaf(xv[f], sm[S_WX + f * 128 + j], a);
                sm[S_ACC + slot * HIDN + j] = a;
                sm[S_H + slot * HIDN + j] = tanhf(a);
            }
            if (lane == 0) {
                si[SI_POS + slot]  = 0;
                si[SI_ACT + slot]  = 1;
                si[SI_GROW + slot] = gr;
            }
        }
        __syncthreads();

        // each warp loops over dense groups of 4
        for (int sbase = 4 * w; sbase < A; sbase += 64) {
            int e  = sbase + 4 < A ? sbase + 4 : A;
            int oe = e < oldc ? e : oldc;
            int no = oe - sbase;
            if (no < 0) no = 0;
            int agrp[4];
            int acnt = 0;
            if (no > 0) {
                int grp[4];
#pragma unroll
                for (int q = 0; q < 4; q++)
                    grp[q] = si[SI_LIST + sbase + (q < no ? q : 0)];
                unsigned mvk = run_old(no, sm, si, noise_tok, noise_c, out, grp, lane);
                if (drain)
                    for (int q = 0; q < no; q++)
                        if ((mvk >> q) & 1) agrp[acnt++] = grp[q];
            }
            int fb = sbase > oldc ? sbase : oldc;
            int nf = e - fb;
            if (nf > 0) {
                int grp[4];
#pragma unroll
                for (int q = 0; q < 4; q++)
                    grp[q] = si[SI_LIST + fb + (q < nf ? q : 0)];
                run_fresh(nf, sm, si, noise_tok, noise_c, out, grp, lane);
            }
            // drain mode: run this group's survivors to completion, no barriers
            while (drain && acnt > 0) {
                int grp[4];
#pragma unroll
                for (int q = 0; q < 4; q++)
                    grp[q] = agrp[q < acnt ? q : 0];
                unsigned mvk = run_old(acnt, sm, si, noise_tok, noise_c, out, grp, lane);
                int nn = 0;
                for (int q = 0; q < acnt; q++)
                    if ((mvk >> q) & 1) agrp[nn++] = grp[q];
                acnt = nn;
            }
        }
        __syncthreads();
        if (drain) break;   // all rows ran to completion above
    }
}

// merged prep + output-init
__global__ void setup_kernel(const float* __restrict__ W_ih, float* __restrict__ out)
{
    int i = blockIdx.x * blockDim.x + threadIdx.x;
    if (i == 0) g_next = 0;
    if (i < INSZ * HIDN) {
        int c = i / HIDN, j = i % HIDN;
        g_WihT[c * HIDN + j] = W_ih[j * INSZ + c];
    }
    float4* o4 = (float4*)out;
    const int n4 = OUT_TOT / 4;
    int stride = gridDim.x * blockDim.x;
    for (int k = i; k < n4; k += stride) {
        float v = (k * 4 < OUT_CV) ? -1.f : 0.f;
        o4[k] = make_float4(v, v, v, v);
    }
}

extern "C" void kernel_launch(void* const* d_in, const int* in_sizes, int n_in,
                              void* d_out, int out_size)
{
    const float* x    = (const float*)d_in[0];
    const float* nt   = (const float*)d_in[1];
    const float* nc   = (const float*)d_in[2];
    const float* wih  = (const float*)d_in[3];
    const float* whh  = (const float*)d_in[4];
    const float* bih  = (const float*)d_in[5];
    const float* bhh  = (const float*)d_in[6];
    const float* wout = (const float*)d_in[7];
    const float* bout = (const float*)d_in[8];
    const float* wc   = (const float*)d_in[9];
    const float* bc   = (const float*)d_in[10];
    float* out = (float*)d_out;

    cudaFuncSetAttribute((const void*)rnn_main,
                         cudaFuncAttributeMaxDynamicSharedMemorySize, SMEM_BYTES);
    setup_kernel<<<512, 256>>>(wih, out);
    rnn_main<<<NBLK, NTH, SMEM_BYTES>>>(x, nt, nc, wih, whh, bih, bhh,
                                        wout, bout, wc, bc, out);
}

// round 10
// speedup vs baseline: 1.5579x; 1.0333x over previous
#include <cuda_runtime.h>
#include <math.h>

#define BSZ    65536
#define TT     31
#define HIDN   128
#define NVOCAB 19
#define NCONST 40
#define INSZ   133
#define SLOTS  96
#define NTH    512
#define NBLK   152

#define OUT_CV  2031616   // BSZ*TT
#define OUT_LP  4063232   // 2*BSZ*TT
#define OUT_TOT 4194304

typedef unsigned long long u64;

// shared float layout
#define S_WHH  0            // float4[kq=32][j=128]
#define S_TOKP 16384        // float4[kq=32][v=32]
#define S_CON  20480        // [k][64]
#define S_H    28672        // [96][128]
#define S_ACC  40960        // [96][128]
#define S_WX   53248        // [f=9][j=128]
#define S_BSUM 54400
#define S_BTOK 54528
#define S_BCON 54560
#define S_LP   54624        // 96
#define S_NF   54720
// int region
#define SI_POS  0
#define SI_SP   96
#define SI_ACT  192
#define SI_T    288
#define SI_GROW 384
#define SI_STK  480         // 96 x 8
#define SI_LIST 1248        // 96
#define SI_DEAD 1344        // 96
#define SI_CNT  1440        // [0]=A [1]=navail [2]=base [3]=oldc
#define SI_N    1444
#define SMEM_BYTES ((S_NF + SI_N) * 4)

#define FULLM 0xffffffffu

__device__ float g_WihT[INSZ * HIDN];   // [c][j]
__device__ int   g_next;

__device__ __forceinline__ u64 ffma2(u64 a, u64 b, u64 c) {
    u64 d;
    asm("fma.rn.f32x2 %0, %1, %2, %3;" : "=l"(d) : "l"(a), "l"(b), "l"(c));
    return d;
}
__device__ __forceinline__ float f2lo(u64 v) { return __uint_as_float((unsigned)v); }
__device__ __forceinline__ float f2hi(u64 v) { return __uint_as_float((unsigned)(v >> 32)); }

__device__ __forceinline__ void lds2(u64& a, u64& b, const float* p) {
    unsigned addr = (unsigned)__cvta_generic_to_shared(p);
    asm("ld.shared.v2.b64 {%0, %1}, [%2];" : "=l"(a), "=l"(b) : "r"(addr));
}

__device__ __forceinline__ float gumbelf(float u) {
    float inner = -logf(u + 1e-9f);
    return -logf(inner + 1e-9f);
}
__device__ __forceinline__ float wmaxf(float v) {
#pragma unroll
    for (int o = 16; o; o >>= 1) v = fmaxf(v, __shfl_xor_sync(FULLM, v, o));
    return v;
}
__device__ __forceinline__ float wsumf(float v) {
#pragma unroll
    for (int o = 16; o; o >>= 1) v += __shfl_xor_sync(FULLM, v, o);
    return v;
}
__device__ __forceinline__ void wargmax(float& s, int& i, float& lp) {
#pragma unroll
    for (int o = 16; o; o >>= 1) {
        float s2 = __shfl_xor_sync(FULLM, s, o);
        int   i2 = __shfl_xor_sync(FULLM, i, o);
        float l2 = __shfl_xor_sync(FULLM, lp, o);
        if (s2 > s || (s2 == s && i2 < i)) { s = s2; i = i2; lp = l2; }
    }
}

// GEMV + tanh + h-store for CNT rows (CNT in {2,4}); math identical to R9.
// Duplicate rows within ONE call are idempotent (all reads precede all writes).
template<int CNT>
__device__ __forceinline__ void phaseA(float* sm, const int* grp, int lane)
{
    u64 zp[CNT][4];
#pragma unroll
    for (int i = 0; i < CNT; i++)
#pragma unroll
        for (int m = 0; m < 4; m++) zp[i][m] = 0ull;
#pragma unroll 4
    for (int kq = 0; kq < 32; kq++) {
        u64 h01[CNT], h23[CNT];
#pragma unroll
        for (int i = 0; i < CNT; i++)
            lds2(h01[i], h23[i], sm + S_H + grp[i] * HIDN + 4 * kq);
#pragma unroll
        for (int m = 0; m < 4; m++) {
            u64 w01, w23;
            lds2(w01, w23, sm + S_WHH + (kq * 128 + lane + 32 * m) * 4);
#pragma unroll
            for (int i = 0; i < CNT; i++) {
                zp[i][m] = ffma2(h01[i], w01, zp[i][m]);
                zp[i][m] = ffma2(h23[i], w23, zp[i][m]);
            }
        }
    }
    float hnew[CNT][4];
#pragma unroll
    for (int i = 0; i < CNT; i++)
#pragma unroll
        for (int m = 0; m < 4; m++) {
            int j = lane + 32 * m;
            float z = f2lo(zp[i][m]) + f2hi(zp[i][m]);
            float a = sm[S_ACC + grp[i] * HIDN + j];
            hnew[i][m] = tanhf(z + a);
        }
    __syncwarp();
#pragma unroll
    for (int i = 0; i < CNT; i++)
#pragma unroll
        for (int m = 0; m < 4; m++)
            sm[S_H + grp[i] * HIDN + lane + 32 * m] = hnew[i][m];
    __syncwarp();
}

// One decode super-step for up to N rows (real count rcnt <= N; slots beyond
// rcnt duplicate grp[0], gated out of all state writes). nold = count of
// non-fresh rows (prefix) needing the recurrent GEMV. Returns survivor mask.
template<int N>
__device__ __forceinline__ unsigned superstep(float* sm, int* si,
                           const float* __restrict__ noise_tok,
                           const float* __restrict__ noise_c,
                           float* __restrict__ out,
                           const int* grp, int rcnt, int nold, int lane)
{
    int p[N], tt[N], gr[N];
    float g_t[N];
#pragma unroll
    for (int i = 0; i < N; i++) {
        int row = grp[i];
        p[i]  = si[SI_POS + row];
        tt[i] = si[SI_T + row];
        gr[i] = si[SI_GROW + row];
        long long bt = (long long)tt[i] * BSZ + gr[i];
        float u = (lane < NVOCAB) ? __ldg(&noise_tok[bt * NVOCAB + lane]) : 0.5f;
        g_t[i] = gumbelf(u);   // overlaps GEMV below
    }

    // Phase A on the old prefix, in sub-calls of 4/2 with in-call duplicate pad
    if (nold > 0) {
        if (N >= 5 && nold >= 5) {
            { int g4[4] = { grp[0], grp[1], grp[2], grp[3] }; phaseA<4>(sm, g4, lane); }
            if (nold == 6) { int g2[2] = { grp[4], grp[5] }; phaseA<2>(sm, g2, lane); }
            else           { int g2[2] = { grp[4], grp[4] }; phaseA<2>(sm, g2, lane); }
        } else if (N >= 3 && nold >= 3) {
            if (nold >= 4) { int g4[4] = { grp[0], grp[1], grp[2], grp[3] }; phaseA<4>(sm, g4, lane); }
            else           { int g4[4] = { grp[0], grp[1], grp[2], grp[0] }; phaseA<4>(sm, g4, lane); }
        } else {
            if (nold == 2) { int g2[2] = { grp[0], grp[1] }; phaseA<2>(sm, g2, lane); }
            else           { int g2[2] = { grp[0], grp[0] }; phaseA<2>(sm, g2, lane); }
        }
    }

    // Phase B: token head logits (lane = vocab index), N-way amortized
    u64 tkp[N];
#pragma unroll
    for (int i = 0; i < N; i++) tkp[i] = 0ull;
#pragma unroll 4
    for (int kq = 0; kq < 32; kq++) {
        u64 w01, w23;
        lds2(w01, w23, sm + S_TOKP + (kq * 32 + lane) * 4);
#pragma unroll
        for (int i = 0; i < N; i++) {
            u64 h01, h23;
            lds2(h01, h23, sm + S_H + grp[i] * HIDN + 4 * kq);
            tkp[i] = ffma2(h01, w01, tkp[i]);
            tkp[i] = ffma2(h23, w23, tkp[i]);
        }
    }
    float btok = sm[S_BTOK + lane];
    const float NEGINF = -INFINITY;

    // Phase C1: batched softmax + Gumbel argmax (N-way ILP on chains)
    float ltok[N];
#pragma unroll
    for (int i = 0; i < N; i++) {
        float l = NEGINF;
        if (lane < NVOCAB) {
            l = f2lo(tkp[i]) + f2hi(tkp[i]) + btok;
            if (p[i] >= 15 && lane < 6) l = NEGINF;
        }
        ltok[i] = l;
    }
    float mx[N];
#pragma unroll
    for (int i = 0; i < N; i++) mx[i] = ltok[i];
#pragma unroll
    for (int o = 16; o; o >>= 1)
#pragma unroll
        for (int i = 0; i < N; i++)
            mx[i] = fmaxf(mx[i], __shfl_xor_sync(FULLM, mx[i], o));
    float sme[N];
#pragma unroll
    for (int i = 0; i < N; i++)
        sme[i] = (lane < NVOCAB) ? expf(ltok[i] - mx[i]) : 0.f;
#pragma unroll
    for (int o = 16; o; o >>= 1)
#pragma unroll
        for (int i = 0; i < N; i++)
            sme[i] += __shfl_xor_sync(FULLM, sme[i], o);
    float sc[N], lpw[N];
    int ci[N];
#pragma unroll
    for (int i = 0; i < N; i++) {
        float lse = logf(sme[i]);
        float lpt = ltok[i] - mx[i] - lse;
        sc[i]  = lpt + g_t[i];
        ci[i]  = lane;
        lpw[i] = lpt;
    }
#pragma unroll
    for (int o = 16; o; o >>= 1) {
#pragma unroll
        for (int i = 0; i < N; i++) {
            float s2 = __shfl_xor_sync(FULLM, sc[i], o);
            int   i2 = __shfl_xor_sync(FULLM, ci[i], o);
            float l2 = __shfl_xor_sync(FULLM, lpw[i], o);
            if (s2 > sc[i] || (s2 == sc[i] && i2 < ci[i])) {
                sc[i] = s2; ci[i] = i2; lpw[i] = l2;
            }
        }
    }

    // Phase C2: rare const head + bookkeeping (only real rows)
    unsigned alive = 0;
#pragma unroll
    for (int i = 0; i < N; i++) {
        if (i >= rcnt) break;
        int row = grp[i];
        int pi  = p[i];
        int choice = ci[i];
        float lp_tok = lpw[i];

        bool is_const = (choice == 18);
        float lp_c = 0.f; int cchoice = 0;
        if (is_const) {   // warp-uniform
            float2 co = make_float2(0.f, 0.f);
#pragma unroll 8
            for (int k4 = 0; k4 < 32; k4++) {
                float4 hv = *(const float4*)(sm + S_H + row * HIDN + 4 * k4);
#pragma unroll
                for (int b = 0; b < 4; b++) {
                    float2 wc = *(const float2*)(sm + S_CON + (4 * k4 + b) * 64 + 2 * lane);
                    float hk = (b == 0) ? hv.x : (b == 1) ? hv.y : (b == 2) ? hv.z : hv.w;
                    co.x = fmaf(hk, wc.x, co.x);
                    co.y = fmaf(hk, wc.y, co.y);
                }
            }
            long long bt = (long long)tt[i] * BSZ + gr[i];
            float2 uc = make_float2(0.f, 0.f);
            if (lane < 20) uc = *(const float2*)(&noise_c[bt * NCONST + 2 * lane]);
            float bc0 = sm[S_BCON + 2 * lane];
            float bc1 = sm[S_BCON + 2 * lane + 1];
            float la = (lane < 20) ? (co.x + bc0) : NEGINF;
            float lb = (lane < 20) ? (co.y + bc1) : NEGINF;
            float mc   = wmaxf(fmaxf(la, lb));
            float ec   = (lane < 20) ? (expf(la - mc) + expf(lb - mc)) : 0.f;
            float lsec = logf(wsumf(ec));
            float lpa = la - mc - lsec;
            float lpb = lb - mc - lsec;
            float sa = lpa + gumbelf(uc.x);
            float sb = lpb + gumbelf(uc.y);
            float s_l, lp_l; int i_l;
            if (sb > sa) { s_l = sb; i_l = 2 * lane + 1; lp_l = lpb; }
            else         { s_l = sa; i_l = 2 * lane;     lp_l = lpa; }
            wargmax(s_l, i_l, lp_l);
            cchoice = i_l; lp_c = lp_l;
        }

        if (lane == 0) {
            float lpn = sm[S_LP + row] + lp_tok + (is_const ? lp_c : 0.f);
            out[gr[i] * TT + pi] = (float)choice;
            if (is_const) out[OUT_CV + gr[i] * TT + pi] = -10.f + 0.5f * (float)cchoice;
            int arity = (choice < 4) ? 2 : ((choice < 6) ? 1 : 0);
            int sp = si[SI_SP + row];
            if (arity == 2) {
                int wsp = sp < 7 ? sp : 7;
                si[SI_STK + row * 8 + wsp] = 2 * pi + 2;
            }
            int sp1 = sp + (arity == 2 ? 1 : 0);
            int nxt, sp2;
            if (arity != 0) { nxt = 2 * pi + 1; sp2 = sp1; }
            else {
                int ridx = sp1 - 1; if (ridx < 0) ridx = 0; if (ridx > 7) ridx = 7;
                nxt = (sp1 > 0) ? si[SI_STK + row * 8 + ridx] : -1;
                sp2 = (sp1 > 0) ? sp1 - 1 : 0;
            }
            if (nxt > TT - 1) nxt = -1;
            if (nxt >= 0) {
                alive |= (1u << i);
                sm[S_LP + row]   = lpn;
                si[SI_POS + row] = nxt;
                si[SI_SP + row]  = sp2;
                si[SI_T + row]   = tt[i] + 1;
            } else {
                si[SI_ACT + row] = 0;
                out[OUT_LP + gr[i]] = lpn;
            }
        }
        if (choice & 15) {
            int cb = 4 * pi;
#pragma unroll
            for (int m = 0; m < 4; m++) {
                int j = lane + 32 * m;
                float a = sm[S_ACC + row * HIDN + j];
#pragma unroll
                for (int b = 0; b < 4; b++)
                    if (choice & (1 << b))
                        a += __ldg(&g_WihT[(cb + b) * HIDN + j]);
                sm[S_ACC + row * HIDN + j] = a;
            }
        }
    }
    alive = __shfl_sync(FULLM, alive, 0);
    __syncwarp();
    return alive;
}

__device__ __forceinline__ unsigned run_n(int n, int nol, float* sm, int* si,
        const float* nt, const float* nc, float* out, const int* grp, int lane)
{
    if (n > 4)      return superstep<6>(sm, si, nt, nc, out, grp, n, nol, lane);
    else if (n > 2) return superstep<4>(sm, si, nt, nc, out, grp, n, nol, lane);
    else            return superstep<2>(sm, si, nt, nc, out, grp, n, nol, lane);
}

__global__ void __launch_bounds__(NTH, 1)
rnn_main(const float* __restrict__ x,
         const float* __restrict__ noise_tok,
         const float* __restrict__ noise_c,
         const float* __restrict__ W_ih,
         const float* __restrict__ W_hh,
         const float* __restrict__ b_ih,
         const float* __restrict__ b_hh,
         const float* __restrict__ W_out,
         const float* __restrict__ b_out,
         const float* __restrict__ W_c,
         const float* __restrict__ b_c,
         float* __restrict__ out)
{
    extern __shared__ float sm[];
    int* si = (int*)(sm + S_NF);
    int tid = threadIdx.x;
    int w = tid >> 5, lane = tid & 31;

    // ---- stage weights ----
    {
        const float4* src = (const float4*)W_hh;   // [j][32]
        float4* dst = (float4*)(sm + S_WHH);
        for (int idx = tid; idx < 32 * 128; idx += NTH) {
            int kq = idx >> 7, j = idx & 127;
            dst[kq * 128 + j] = src[j * 32 + kq];
        }
    }
    {
        float4* dst = (float4*)(sm + S_TOKP);
        const float4 z4 = make_float4(0.f, 0.f, 0.f, 0.f);
        const float4* src = (const float4*)W_out;  // [v][32]
        for (int idx = tid; idx < 32 * 32; idx += NTH) {
            int kq = idx >> 5, v = idx & 31;
            dst[kq * 32 + v] = (v < NVOCAB) ? src[v * 32 + kq] : z4;
        }
    }
    for (int idx = tid; idx < HIDN * 64; idx += NTH) sm[S_CON + idx] = 0.f;
    __syncthreads();
    for (int idx = tid; idx < NCONST * HIDN; idx += NTH) {
        int c = idx / HIDN, k = idx % HIDN;
        sm[S_CON + k * 64 + c] = W_c[idx];
    }
    for (int idx = tid; idx < 9 * HIDN; idx += NTH) {
        int f = idx >> 7, j = idx & 127;
        sm[S_WX + f * 128 + j] = W_ih[j * INSZ + 124 + f];
    }
    if (tid < HIDN) sm[S_BSUM + tid] = b_ih[tid] + b_hh[tid];
    if (tid < 32) sm[S_BTOK + tid] = (tid < NVOCAB) ? b_out[tid] : 0.f;
    if (tid < 64) sm[S_BCON + tid] = (tid < NCONST) ? b_c[tid] : 0.f;
    if (tid < SLOTS) si[SI_ACT + tid] = 0;
    __syncthreads();

    // ---- persistent work loop (2 barriers per round) ----
    for (;;) {
        if (w == 0) {
            unsigned lt = (1u << lane) - 1u;
            int nold = 0, ndead = 0;
            unsigned am[3];
            int po[3], pd[3];
#pragma unroll
            for (int c = 0; c < 3; c++) {
                int act = si[SI_ACT + 32 * c + lane];
                unsigned m = __ballot_sync(FULLM, act != 0);
                am[c] = m; po[c] = nold; pd[c] = ndead;
                nold  += __popc(m);
                ndead += 32 - __popc(m);
            }
            int base = 0;
            if (lane == 0 && ndead > 0) base = atomicAdd(&g_next, ndead);
            base = __shfl_sync(FULLM, base, 0);
            int navail = BSZ - base;
            if (navail < 0) navail = 0;
            if (navail > ndead) navail = ndead;
#pragma unroll
            for (int c = 0; c < 3; c++) {
                int slot = 32 * c + lane;
                if ((am[c] >> lane) & 1) si[SI_LIST + po[c] + __popc(am[c] & lt)] = slot;
                else                     si[SI_DEAD + pd[c] + __popc(~am[c] & lt)] = slot;
            }
            __syncwarp();
            for (int q = lane; q < navail; q += 32)
                si[SI_LIST + nold + q] = si[SI_DEAD + q];
            if (lane == 0) {
                si[SI_CNT]     = nold + navail;
                si[SI_CNT + 1] = navail;
                si[SI_CNT + 2] = (ndead > 0) ? base : 0;
                si[SI_CNT + 3] = nold;
            }
        }
        __syncthreads();
        int A = si[SI_CNT];
        int navail = si[SI_CNT + 1];
        int rbase  = si[SI_CNT + 2];
        int oldc   = si[SI_CNT + 3];
        if (A == 0) break;
        bool drain = (navail == 0) && (rbase >= BSZ);   // pool empty forever

        // this warp's contiguous chunk of the active list
        int lo = (A * w) >> 4;
        int hi = (A * (w + 1)) >> 4;

        // owner-refill: init this warp's fresh rows (h = tanh(acc); step-0 GEMV = 0)
        int fstart = lo > oldc ? lo : oldc;
        for (int idx = fstart; idx < hi; idx++) {
            int slot = si[SI_LIST + idx];
            int gr = rbase + (idx - oldc);
            float xv[9];
#pragma unroll
            for (int f = 0; f < 9; f++) xv[f] = __ldg(&x[gr * 9 + f]);
#pragma unroll
            for (int m = 0; m < 4; m++) {
                int j = lane + 32 * m;
                float a = sm[S_BSUM + j];
#pragma unroll
                for (int f = 0; f < 9; f++) a = fmaf(xv[f], sm[S_WX + f * 128 + j], a);
                sm[S_ACC + slot * HIDN + j] = a;
                sm[S_H + slot * HIDN + j] = tanhf(a);
            }
            if (lane == 0) {
                si[SI_POS + slot]  = 0;
                si[SI_SP + slot]   = 0;
                si[SI_T + slot]    = 0;
                si[SI_ACT + slot]  = 1;
                si[SI_GROW + slot] = gr;
                sm[S_LP + slot]    = 0.f;
            }
        }
        __syncwarp();

        // super-steps of up to 6 rows
        for (int base = lo; base < hi; base += 6) {
            int n = hi - base; if (n > 6) n = 6;
            int grp[6];
#pragma unroll
            for (int q = 0; q < 6; q++)
                grp[q] = si[SI_LIST + base + (q < n ? q : 0)];
            int nol = oldc - base;
            if (nol < 0) nol = 0;
            if (nol > n) nol = n;
            unsigned mv = run_n(n, nol, sm, si, noise_tok, noise_c, out, grp, lane);

            // drain mode: run this chunk's survivors to completion, no barriers
            while (drain && mv) {
                int ag[6]; int cnt = 0;
                for (int q = 0; q < n; q++)
                    if ((mv >> q) & 1) ag[cnt++] = grp[q];
                n = cnt;
                for (int q = 0; q < 6; q++) grp[q] = ag[q < n ? q : 0];
                mv = run_n(n, n, sm, si, noise_tok, noise_c, out, grp, lane);
            }
        }
        __syncthreads();
        if (drain) break;   // all remaining rows ran to completion above
    }
}

// merged prep + output-init
__global__ void setup_kernel(const float* __restrict__ W_ih, float* __restrict__ out)
{
    int i = blockIdx.x * blockDim.x + threadIdx.x;
    if (i == 0) g_next = 0;
    if (i < INSZ * HIDN) {
        int c = i / HIDN, j = i % HIDN;
        g_WihT[c * HIDN + j] = W_ih[j * INSZ + c];
    }
    float4* o4 = (float4*)out;
    const int n4 = OUT_TOT / 4;
    int stride = gridDim.x * blockDim.x;
    for (int k = i; k < n4; k += stride) {
        float v = (k * 4 < OUT_CV) ? -1.f : 0.f;
        o4[k] = make_float4(v, v, v, v);
    }
}

extern "C" void kernel_launch(void* const* d_in, const int* in_sizes, int n_in,
                              void* d_out, int out_size)
{
    const float* x    = (const float*)d_in[0];
    const float* nt   = (const float*)d_in[1];
    const float* nc   = (const float*)d_in[2];
    const float* wih  = (const float*)d_in[3];
    const float* whh  = (const float*)d_in[4];
    const float* bih  = (const float*)d_in[5];
    const float* bhh  = (const float*)d_in[6];
    const float* wout = (const float*)d_in[7];
    const float* bout = (const float*)d_in[8];
    const float* wc   = (const float*)d_in[9];
    const float* bc   = (const float*)d_in[10];
    float* out = (float*)d_out;

    cudaFuncSetAttribute((const void*)rnn_main,
                         cudaFuncAttributeMaxDynamicSharedMemorySize, SMEM_BYTES);
    setup_kernel<<<512, 256>>>(wih, out);
    rnn_main<<<NBLK, NTH, SMEM_BYTES>>>(x, nt, nc, wih, whh, bih, bhh,
                                        wout, bout, wc, bc, out);
}

// round 12
// speedup vs baseline: 1.6605x; 1.0658x over previous
#include <cuda_runtime.h>
#include <math.h>

#define BSZ    65536
#define TT     31
#define HIDN   128
#define NVOCAB 19
#define NCONST 40
#define INSZ   133
#define SLOTS  96
#define NTH    512
#define NBLK   152

#define OUT_CV  2031616   // BSZ*TT
#define OUT_LP  4063232   // 2*BSZ*TT
#define OUT_TOT 4194304

typedef unsigned long long u64;

// shared float layout
#define S_WHH  0            // float4[kq=32][j=128]
#define S_TOKP 16384        // float4[kq=32][v=32]
#define S_CON  20480        // [k][64]
#define S_H    28672        // [96][128]
#define S_ACC  40960        // [96][128]
#define S_WX   53248        // [f=9][j=128]
#define S_BSUM 54400
#define S_BTOK 54528
#define S_BCON 54560
#define S_LP   54624        // 96
#define S_NF   54720
// int region
#define SI_POS  0
#define SI_SP   96
#define SI_ACT  192
#define SI_T    288
#define SI_GROW 384
#define SI_STK  480         // 96 x 8
#define SI_LIST 1248        // 96
#define SI_DEAD 1344        // 96
#define SI_CNT  1440        // [0]=A [1]=navail [2]=base [3]=oldc
#define SI_N    1444
#define SMEM_BYTES ((S_NF + SI_N) * 4)

#define FULLM 0xffffffffu

__device__ float g_WihT[INSZ * HIDN];   // [c][j]
__device__ int   g_next;

__device__ __forceinline__ u64 ffma2(u64 a, u64 b, u64 c) {
    u64 d;
    asm("fma.rn.f32x2 %0, %1, %2, %3;" : "=l"(d) : "l"(a), "l"(b), "l"(c));
    return d;
}
__device__ __forceinline__ float f2lo(u64 v) { return __uint_as_float((unsigned)v); }
__device__ __forceinline__ float f2hi(u64 v) { return __uint_as_float((unsigned)(v >> 32)); }

__device__ __forceinline__ void lds2(u64& a, u64& b, const float* p) {
    unsigned addr = (unsigned)__cvta_generic_to_shared(p);
    asm("ld.shared.v2.b64 {%0, %1}, [%2];" : "=l"(a), "=l"(b) : "r"(addr));
}

__device__ __forceinline__ float wmaxf(float v) {
#pragma unroll
    for (int o = 16; o; o >>= 1) v = fmaxf(v, __shfl_xor_sync(FULLM, v, o));
    return v;
}
__device__ __forceinline__ float wsumf(float v) {
#pragma unroll
    for (int o = 16; o; o >>= 1) v += __shfl_xor_sync(FULLM, v, o);
    return v;
}

__device__ __forceinline__ float gumbelf(float u) {
    float inner = -logf(u + 1e-9f);
    return -logf(inner + 1e-9f);
}

// GEMV + tanh + h-store for CNT rows (CNT in {2,4}); duplicate rows within one
// call are idempotent (all reads precede all writes).
template<int CNT>
__device__ __forceinline__ void phaseA(float* sm, const int* grp, int lane)
{
    u64 zp[CNT][4];
#pragma unroll
    for (int i = 0; i < CNT; i++)
#pragma unroll
        for (int m = 0; m < 4; m++) zp[i][m] = 0ull;
#pragma unroll 4
    for (int kq = 0; kq < 32; kq++) {
        u64 h01[CNT], h23[CNT];
#pragma unroll
        for (int i = 0; i < CNT; i++)
            lds2(h01[i], h23[i], sm + S_H + grp[i] * HIDN + 4 * kq);
#pragma unroll
        for (int m = 0; m < 4; m++) {
            u64 w01, w23;
            lds2(w01, w23, sm + S_WHH + (kq * 128 + lane + 32 * m) * 4);
#pragma unroll
            for (int i = 0; i < CNT; i++) {
                zp[i][m] = ffma2(h01[i], w01, zp[i][m]);
                zp[i][m] = ffma2(h23[i], w23, zp[i][m]);
            }
        }
    }
    float hnew[CNT][4];
#pragma unroll
    for (int i = 0; i < CNT; i++)
#pragma unroll
        for (int m = 0; m < 4; m++) {
            int j = lane + 32 * m;
            float z = f2lo(zp[i][m]) + f2hi(zp[i][m]);
            float a = sm[S_ACC + grp[i] * HIDN + j];
            hnew[i][m] = tanhf(z + a);
        }
    __syncwarp();
#pragma unroll
    for (int i = 0; i < CNT; i++)
#pragma unroll
        for (int m = 0; m < 4; m++)
            sm[S_H + grp[i] * HIDN + lane + 32 * m] = hnew[i][m];
    __syncwarp();
}

// One decode super-step for up to N rows (real count rcnt <= N; slots beyond
// rcnt duplicate grp[0], gated out of all state writes). nold = count of
// non-fresh rows (prefix) needing the recurrent GEMV. Returns survivor mask.
template<int N>
__device__ __forceinline__ unsigned superstep(float* sm, int* si,
                           const float* __restrict__ noise_tok,
                           const float* __restrict__ noise_c,
                           float* __restrict__ out,
                           const int* grp, int rcnt, int nold, int lane)
{
    int p[N], tt[N], gr[N];
    float g_t[N];
#pragma unroll
    for (int i = 0; i < N; i++) {
        int row = grp[i];
        p[i]  = si[SI_POS + row];
        tt[i] = si[SI_T + row];
        gr[i] = si[SI_GROW + row];
        long long bt = (long long)tt[i] * BSZ + gr[i];
        float u = (lane < NVOCAB) ? __ldg(&noise_tok[bt * NVOCAB + lane]) : 0.5f;
        g_t[i] = gumbelf(u);   // overlaps GEMV below
    }

    // Phase A on the old prefix, in sub-calls of 4/2 with in-call duplicate pad
    if (nold > 0) {
        if (N >= 5 && nold >= 5) {
            { int g4[4] = { grp[0], grp[1], grp[2], grp[3] }; phaseA<4>(sm, g4, lane); }
            if (nold == 6) { int g2[2] = { grp[4], grp[5] }; phaseA<2>(sm, g2, lane); }
            else           { int g2[2] = { grp[4], grp[4] }; phaseA<2>(sm, g2, lane); }
        } else if (N >= 3 && nold >= 3) {
            if (nold >= 4) { int g4[4] = { grp[0], grp[1], grp[2], grp[3] }; phaseA<4>(sm, g4, lane); }
            else           { int g4[4] = { grp[0], grp[1], grp[2], grp[0] }; phaseA<4>(sm, g4, lane); }
        } else {
            if (nold == 2) { int g2[2] = { grp[0], grp[1] }; phaseA<2>(sm, g2, lane); }
            else           { int g2[2] = { grp[0], grp[0] }; phaseA<2>(sm, g2, lane); }
        }
    }

    // Phase B: token head logits (lane = vocab index), N-way amortized
    u64 tkp[N];
#pragma unroll
    for (int i = 0; i < N; i++) tkp[i] = 0ull;
#pragma unroll 4
    for (int kq = 0; kq < 32; kq++) {
        u64 w01, w23;
        lds2(w01, w23, sm + S_TOKP + (kq * 32 + lane) * 4);
#pragma unroll
        for (int i = 0; i < N; i++) {
            u64 h01, h23;
            lds2(h01, h23, sm + S_H + grp[i] * HIDN + 4 * kq);
            tkp[i] = ffma2(h01, w01, tkp[i]);
            tkp[i] = ffma2(h23, w23, tkp[i]);
        }
    }
    float btok = sm[S_BTOK + lane];
    const float NEGINF = -INFINITY;

    // Phase C1: batched softmax + Gumbel argmax (ballot-based argmax)
    float ltok[N];
#pragma unroll
    for (int i = 0; i < N; i++) {
        float l = NEGINF;
        if (lane < NVOCAB) {
            l = f2lo(tkp[i]) + f2hi(tkp[i]) + btok;
            if (p[i] >= 15 && lane < 6) l = NEGINF;
        }
        ltok[i] = l;
    }
    float mx[N];
#pragma unroll
    for (int i = 0; i < N; i++) mx[i] = ltok[i];
#pragma unroll
    for (int o = 16; o; o >>= 1)
#pragma unroll
        for (int i = 0; i < N; i++)
            mx[i] = fmaxf(mx[i], __shfl_xor_sync(FULLM, mx[i], o));
    float sme[N];
#pragma unroll
    for (int i = 0; i < N; i++)
        sme[i] = (lane < NVOCAB) ? expf(ltok[i] - mx[i]) : 0.f;
#pragma unroll
    for (int o = 16; o; o >>= 1)
#pragma unroll
        for (int i = 0; i < N; i++)
            sme[i] += __shfl_xor_sync(FULLM, sme[i], o);
    float lpt[N], sc[N];
#pragma unroll
    for (int i = 0; i < N; i++) {
        float lse = logf(sme[i]);
        lpt[i] = ltok[i] - mx[i] - lse;
        sc[i]  = lpt[i] + g_t[i];
    }
    float scm[N];
#pragma unroll
    for (int i = 0; i < N; i++) scm[i] = sc[i];
#pragma unroll
    for (int o = 16; o; o >>= 1)
#pragma unroll
        for (int i = 0; i < N; i++)
            scm[i] = fmaxf(scm[i], __shfl_xor_sync(FULLM, scm[i], o));
    int ci[N];
    float lpw[N];
#pragma unroll
    for (int i = 0; i < N; i++) {
        unsigned b = __ballot_sync(FULLM, sc[i] == scm[i]);
        int widx = __ffs(b) - 1;        // first (lowest-index) max = jnp.argmax
        ci[i]  = widx;
        lpw[i] = __shfl_sync(FULLM, lpt[i], widx);
    }

    // Phase C2: rare const head + bookkeeping (only real rows)
    unsigned alive = 0;
#pragma unroll
    for (int i = 0; i < N; i++) {
        if (i >= rcnt) break;
        int row = grp[i];
        int pi  = p[i];
        int choice = ci[i];
        float lp_tok = lpw[i];

        bool is_const = (choice == 18);
        float lp_c = 0.f; int cchoice = 0;
        if (is_const) {   // warp-uniform
            float2 co = make_float2(0.f, 0.f);
#pragma unroll 8
            for (int k4 = 0; k4 < 32; k4++) {
                float4 hv = *(const float4*)(sm + S_H + row * HIDN + 4 * k4);
#pragma unroll
                for (int b = 0; b < 4; b++) {
                    float2 wc = *(const float2*)(sm + S_CON + (4 * k4 + b) * 64 + 2 * lane);
                    float hk = (b == 0) ? hv.x : (b == 1) ? hv.y : (b == 2) ? hv.z : hv.w;
                    co.x = fmaf(hk, wc.x, co.x);
                    co.y = fmaf(hk, wc.y, co.y);
                }
            }
            long long bt = (long long)tt[i] * BSZ + gr[i];
            float2 uc = make_float2(0.f, 0.f);
            if (lane < 20) uc = *(const float2*)(&noise_c[bt * NCONST + 2 * lane]);
            float bc0 = sm[S_BCON + 2 * lane];
            float bc1 = sm[S_BCON + 2 * lane + 1];
            float la = (lane < 20) ? (co.x + bc0) : NEGINF;
            float lb = (lane < 20) ? (co.y + bc1) : NEGINF;
            float mc   = wmaxf(fmaxf(la, lb));
            float ec   = (lane < 20) ? (expf(la - mc) + expf(lb - mc)) : 0.f;
            float lsec = logf(wsumf(ec));
            float lpa = la - mc - lsec;
            float lpb = lb - mc - lsec;
            float sa = lpa + gumbelf(uc.x);
            float sb = lpb + gumbelf(uc.y);
            // within-lane pick (tie -> lower index), then cross-lane first-max
            float s_l, lp_l; int i_l;
            if (sb > sa) { s_l = sb; i_l = 2 * lane + 1; lp_l = lpb; }
            else         { s_l = sa; i_l = 2 * lane;     lp_l = lpa; }
            float m2 = wmaxf(s_l);
            unsigned b2 = __ballot_sync(FULLM, s_l == m2);
            int wl = __ffs(b2) - 1;     // lowest lane among maxes = lowest index
            cchoice = __shfl_sync(FULLM, i_l, wl);
            lp_c    = __shfl_sync(FULLM, lp_l, wl);
        }

        if (lane == 0) {
            float lpn = sm[S_LP + row] + lp_tok + (is_const ? lp_c : 0.f);
            out[gr[i] * TT + pi] = (float)choice;
            if (is_const) out[OUT_CV + gr[i] * TT + pi] = -10.f + 0.5f * (float)cchoice;
            int arity = (choice < 4) ? 2 : ((choice < 6) ? 1 : 0);
            int sp = si[SI_SP + row];
            if (arity == 2) {
                int wsp = sp < 7 ? sp : 7;
                si[SI_STK + row * 8 + wsp] = 2 * pi + 2;
            }
            int sp1 = sp + (arity == 2 ? 1 : 0);
            int nxt, sp2;
            if (arity != 0) { nxt = 2 * pi + 1; sp2 = sp1; }
            else {
                int ridx = sp1 - 1; if (ridx < 0) ridx = 0; if (ridx > 7) ridx = 7;
                nxt = (sp1 > 0) ? si[SI_STK + row * 8 + ridx] : -1;
                sp2 = (sp1 > 0) ? sp1 - 1 : 0;
            }
            if (nxt > TT - 1) nxt = -1;
            if (nxt >= 0) {
                alive |= (1u << i);
                sm[S_LP + row]   = lpn;
                si[SI_POS + row] = nxt;
                si[SI_SP + row]  = sp2;
                si[SI_T + row]   = tt[i] + 1;
            } else {
                si[SI_ACT + row] = 0;
                out[OUT_LP + gr[i]] = lpn;
            }
        }
        if (choice & 15) {
            int cb = 4 * pi;
#pragma unroll
            for (int m = 0; m < 4; m++) {
                int j = lane + 32 * m;
                float a = sm[S_ACC + row * HIDN + j];
#pragma unroll
                for (int b = 0; b < 4; b++)
                    if (choice & (1 << b))
                        a += __ldg(&g_WihT[(cb + b) * HIDN + j]);
                sm[S_ACC + row * HIDN + j] = a;
            }
        }
    }
    alive = __shfl_sync(FULLM, alive, 0);
    __syncwarp();
    return alive;
}

__device__ __forceinline__ unsigned run_n(int n, int nol, float* sm, int* si,
        const float* nt, const float* nc, float* out, const int* grp, int lane)
{
    if (n > 4)      return superstep<6>(sm, si, nt, nc, out, grp, n, nol, lane);
    else if (n > 2) return superstep<4>(sm, si, nt, nc, out, grp, n, nol, lane);
    else            return superstep<2>(sm, si, nt, nc, out, grp, n, nol, lane);
}

__global__ void __launch_bounds__(NTH, 1)
rnn_main(const float* __restrict__ x,
         const float* __restrict__ noise_tok,
         const float* __restrict__ noise_c,
         const float* __restrict__ W_ih,
         const float* __restrict__ W_hh,
         const float* __restrict__ b_ih,
         const float* __restrict__ b_hh,
         const float* __restrict__ W_out,
         const float* __restrict__ b_out,
         const float* __restrict__ W_c,
         const float* __restrict__ b_c,
         float* __restrict__ out)
{
    extern __shared__ float sm[];
    int* si = (int*)(sm + S_NF);
    int tid = threadIdx.x;
    int w = tid >> 5, lane = tid & 31;

    // ---- stage weights ----
    {
        const float4* src = (const float4*)W_hh;   // [j][32]
        float4* dst = (float4*)(sm + S_WHH);
        for (int idx = tid; idx < 32 * 128; idx += NTH) {
            int kq = idx >> 7, j = idx & 127;
            dst[kq * 128 + j] = src[j * 32 + kq];
        }
    }
    {
        float4* dst = (float4*)(sm + S_TOKP);
        const float4 z4 = make_float4(0.f, 0.f, 0.f, 0.f);
        const float4* src = (const float4*)W_out;  // [v][32]
        for (int idx = tid; idx < 32 * 32; idx += NTH) {
            int kq = idx >> 5, v = idx & 31;
            dst[kq * 32 + v] = (v < NVOCAB) ? src[v * 32 + kq] : z4;
        }
    }
    for (int idx = tid; idx < HIDN * 64; idx += NTH) sm[S_CON + idx] = 0.f;
    __syncthreads();
    for (int idx = tid; idx < NCONST * HIDN; idx += NTH) {
        int c = idx / HIDN, k = idx % HIDN;
        sm[S_CON + k * 64 + c] = W_c[idx];
    }
    for (int idx = tid; idx < 9 * HIDN; idx += NTH) {
        int f = idx >> 7, j = idx & 127;
        sm[S_WX + f * 128 + j] = W_ih[j * INSZ + 124 + f];
    }
    if (tid < HIDN) sm[S_BSUM + tid] = b_ih[tid] + b_hh[tid];
    if (tid < 32) sm[S_BTOK + tid] = (tid < NVOCAB) ? b_out[tid] : 0.f;
    if (tid < 64) sm[S_BCON + tid] = (tid < NCONST) ? b_c[tid] : 0.f;
    if (tid < SLOTS) si[SI_ACT + tid] = 0;
    __syncthreads();

    // ---- persistent work loop (2 barriers per round) ----
    for (;;) {
        if (w == 0) {
            unsigned lt = (1u << lane) - 1u;
            int nold = 0, ndead = 0;
            unsigned am[3];
            int po[3], pd[3];
#pragma unroll
            for (int c = 0; c < 3; c++) {
                int act = si[SI_ACT + 32 * c + lane];
                unsigned m = __ballot_sync(FULLM, act != 0);
                am[c] = m; po[c] = nold; pd[c] = ndead;
                nold  += __popc(m);
                ndead += 32 - __popc(m);
            }
            int base = 0;
            if (lane == 0 && ndead > 0) base = atomicAdd(&g_next, ndead);
            base = __shfl_sync(FULLM, base, 0);
            int navail = BSZ - base;
            if (navail < 0) navail = 0;
            if (navail > ndead) navail = ndead;
#pragma unroll
            for (int c = 0; c < 3; c++) {
                int slot = 32 * c + lane;
                if ((am[c] >> lane) & 1) si[SI_LIST + po[c] + __popc(am[c] & lt)] = slot;
                else                     si[SI_DEAD + pd[c] + __popc(~am[c] & lt)] = slot;
            }
            __syncwarp();
            for (int q = lane; q < navail; q += 32)
                si[SI_LIST + nold + q] = si[SI_DEAD + q];
            if (lane == 0) {
                si[SI_CNT]     = nold + navail;
                si[SI_CNT + 1] = navail;
                si[SI_CNT + 2] = (ndead > 0) ? base : 0;
                si[SI_CNT + 3] = nold;
            }
        }
        __syncthreads();
        int A = si[SI_CNT];
        int navail = si[SI_CNT + 1];
        int rbase  = si[SI_CNT + 2];
        int oldc   = si[SI_CNT + 3];
        if (A == 0) break;
        bool drain = (navail == 0) && (rbase >= BSZ);   // pool empty forever

        // this warp's contiguous chunk of the active list
        int lo = (A * w) >> 4;
        int hi = (A * (w + 1)) >> 4;

        // owner-refill: init this warp's fresh rows (h = tanh(acc); step-0 GEMV = 0)
        int fstart = lo > oldc ? lo : oldc;
        for (int idx = fstart; idx < hi; idx++) {
            int slot = si[SI_LIST + idx];
            int gr = rbase + (idx - oldc);
            float xv[9];
#pragma unroll
            for (int f = 0; f < 9; f++) xv[f] = __ldg(&x[gr * 9 + f]);
#pragma unroll
            for (int m = 0; m < 4; m++) {
                int j = lane + 32 * m;
                float a = sm[S_BSUM + j];
#pragma unroll
                for (int f = 0; f < 9; f++) a = fmaf(xv[f], sm[S_WX + f * 128 + j], a);
                sm[S_ACC + slot * HIDN + j] = a;
                sm[S_H + slot * HIDN + j] = tanhf(a);
            }
            // default-init this row's output slice (each row refilled exactly once)
            if (lane < TT) {
                out[gr * TT + lane] = -1.f;
                out[OUT_CV + gr * TT + lane] = 0.f;
            }
            if (lane == 0) {
                si[SI_POS + slot]  = 0;
                si[SI_SP + slot]   = 0;
                si[SI_T + slot]    = 0;
                si[SI_ACT + slot]  = 1;
                si[SI_GROW + slot] = gr;
                sm[S_LP + slot]    = 0.f;
            }
        }
        __syncwarp();

        // super-steps of up to 6 rows
        for (int base = lo; base < hi; base += 6) {
            int n = hi - base; if (n > 6) n = 6;
            int grp[6];
#pragma unroll
            for (int q = 0; q < 6; q++)
                grp[q] = si[SI_LIST + base + (q < n ? q : 0)];
            int nol = oldc - base;
            if (nol < 0) nol = 0;
            if (nol > n) nol = n;
            unsigned mv = run_n(n, nol, sm, si, noise_tok, noise_c, out, grp, lane);

            // drain mode: run this chunk's survivors to completion, no barriers
            while (drain && mv) {
                int ag[6]; int cnt = 0;
                for (int q = 0; q < n; q++)
                    if ((mv >> q) & 1) ag[cnt++] = grp[q];
                n = cnt;
                for (int q = 0; q < 6; q++) grp[q] = ag[q < n ? q : 0];
                mv = run_n(n, n, sm, si, noise_tok, noise_c, out, grp, lane);
            }
        }
        __syncthreads();
        if (drain) break;   // all remaining rows ran to completion above
    }
}

// prep only (out-init now handled per-row at refill time)
__global__ void setup_kernel(const float* __restrict__ W_ih)
{
    int i = blockIdx.x * blockDim.x + threadIdx.x;
    if (i == 0) g_next = 0;
    if (i < INSZ * HIDN) {
        int c = i / HIDN, j = i % HIDN;
        g_WihT[c * HIDN + j] = W_ih[j * INSZ + c];
    }
}

extern "C" void kernel_launch(void* const* d_in, const int* in_sizes, int n_in,
                              void* d_out, int out_size)
{
    const float* x    = (const float*)d_in[0];
    const float* nt   = (const float*)d_in[1];
    const float* nc   = (const float*)d_in[2];
    const float* wih  = (const float*)d_in[3];
    const float* whh  = (const float*)d_in[4];
    const float* bih  = (const float*)d_in[5];
    const float* bhh  = (const float*)d_in[6];
    const float* wout = (const float*)d_in[7];
    const float* bout = (const float*)d_in[8];
    const float* wc   = (const float*)d_in[9];
    const float* bc   = (const float*)d_in[10];
    float* out = (float*)d_out;

    cudaFuncSetAttribute((const void*)rnn_main,
                         cudaFuncAttributeMaxDynamicSharedMemorySize, SMEM_BYTES);
    setup_kernel<<<(INSZ * HIDN + 255) / 256, 256>>>(wih);
    rnn_main<<<NBLK, NTH, SMEM_BYTES>>>(x, nt, nc, wih, whh, bih, bhh,
                                        wout, bout, wc, bc, out);
}

// round 13
// speedup vs baseline: 1.7036x; 1.0260x over previous
#include <cuda_runtime.h>
#include <math.h>

#define BSZ    65536
#define TT     31
#define HIDN   128
#define NVOCAB 19
#define NCONST 40
#define INSZ   133
#define SLOTS  96
#define NTH    512
#define NBLK   152

#define OUT_CV  2031616   // BSZ*TT
#define OUT_LP  4063232   // 2*BSZ*TT
#define OUT_TOT 4194304

typedef unsigned long long u64;

// shared float layout
#define S_WHH  0            // float4[kq=32][j=128]
#define S_TOKP 16384        // float4[kq=32][v=32]
#define S_CON  20480        // [k][64]
#define S_H    28672        // [96][128]
#define S_ACC  40960        // [96][128]
#define S_WX   53248        // [f=9][j=128]
#define S_BSUM 54400
#define S_BTOK 54528
#define S_BCON 54560
#define S_LP   54624        // 96
#define S_NF   54720
// int region
#define SI_POS  0
#define SI_SP   96
#define SI_ACT  192
#define SI_T    288
#define SI_GROW 384
#define SI_STK  480         // 96 x 8
#define SI_LIST 1248        // 96
#define SI_DEAD 1344        // 96
#define SI_CNT  1440        // [0]=A [1]=navail [2]=base [3]=oldc
#define SI_N    1444
#define SMEM_BYTES ((S_NF + SI_N) * 4)

#define FULLM 0xffffffffu

__device__ float g_WihT[INSZ * HIDN];   // [c][j]
__device__ int   g_next;

__device__ __forceinline__ u64 ffma2(u64 a, u64 b, u64 c) {
    u64 d;
    asm("fma.rn.f32x2 %0, %1, %2, %3;" : "=l"(d) : "l"(a), "l"(b), "l"(c));
    return d;
}
__device__ __forceinline__ float f2lo(u64 v) { return __uint_as_float((unsigned)v); }
__device__ __forceinline__ float f2hi(u64 v) { return __uint_as_float((unsigned)(v >> 32)); }

__device__ __forceinline__ void lds2(u64& a, u64& b, const float* p) {
    unsigned addr = (unsigned)__cvta_generic_to_shared(p);
    asm("ld.shared.v2.b64 {%0, %1}, [%2];" : "=l"(a), "=l"(b) : "r"(addr));
}

// warp max of f32 via order-preserving s32 map + redux.sync.max.s32 (sm_80+).
// map k = b ^ ((b>>31)&0x7FFFFFFF) is a monotone involution for non-NaN floats,
// so the result is bit-exact equal to the true maximum input.
__device__ __forceinline__ float rmaxf(float v) {
    int b = __float_as_int(v);
    int k = b ^ ((b >> 31) & 0x7FFFFFFF);
    int r;
    asm("redux.sync.max.s32 %0, %1, 0xffffffff;" : "=r"(r) : "r"(k));
    return __int_as_float(r ^ ((r >> 31) & 0x7FFFFFFF));
}
// warp sum via fixed-point redux.add.s32; SCALE chosen so no overflow.
__device__ __forceinline__ float rsumf(float v, float scale, float inv_scale) {
    int fx = (int)(v * scale);
    int r;
    asm("redux.sync.add.s32 %0, %1, 0xffffffff;" : "=r"(r) : "r"(fx));
    return (float)r * inv_scale;
}

__device__ __forceinline__ float gumbelf(float u) {
    float inner = -logf(u + 1e-9f);
    return -logf(inner + 1e-9f);
}

// GEMV + tanh + h-store for CNT rows (CNT in {2,4}); duplicate rows within one
// call are idempotent (all reads precede all writes).
template<int CNT>
__device__ __forceinline__ void phaseA(float* sm, const int* grp, int lane)
{
    u64 zp[CNT][4];
#pragma unroll
    for (int i = 0; i < CNT; i++)
#pragma unroll
        for (int m = 0; m < 4; m++) zp[i][m] = 0ull;
#pragma unroll 4
    for (int kq = 0; kq < 32; kq++) {
        u64 h01[CNT], h23[CNT];
#pragma unroll
        for (int i = 0; i < CNT; i++)
            lds2(h01[i], h23[i], sm + S_H + grp[i] * HIDN + 4 * kq);
#pragma unroll
        for (int m = 0; m < 4; m++) {
            u64 w01, w23;
            lds2(w01, w23, sm + S_WHH + (kq * 128 + lane + 32 * m) * 4);
#pragma unroll
            for (int i = 0; i < CNT; i++) {
                zp[i][m] = ffma2(h01[i], w01, zp[i][m]);
                zp[i][m] = ffma2(h23[i], w23, zp[i][m]);
            }
        }
    }
    float hnew[CNT][4];
#pragma unroll
    for (int i = 0; i < CNT; i++)
#pragma unroll
        for (int m = 0; m < 4; m++) {
            int j = lane + 32 * m;
            float z = f2lo(zp[i][m]) + f2hi(zp[i][m]);
            float a = sm[S_ACC + grp[i] * HIDN + j];
            hnew[i][m] = tanhf(z + a);
        }
    __syncwarp();
#pragma unroll
    for (int i = 0; i < CNT; i++)
#pragma unroll
        for (int m = 0; m < 4; m++)
            sm[S_H + grp[i] * HIDN + lane + 32 * m] = hnew[i][m];
    __syncwarp();
}

// One decode super-step for up to N rows (real count rcnt <= N; slots beyond
// rcnt duplicate grp[0], gated out of all state writes). nold = count of
// non-fresh rows (prefix) needing the recurrent GEMV. Returns survivor mask.
template<int N>
__device__ __forceinline__ unsigned superstep(float* sm, int* si,
                           const float* __restrict__ noise_tok,
                           const float* __restrict__ noise_c,
                           float* __restrict__ out,
                           const int* grp, int rcnt, int nold, int lane)
{
    int p[N], tt[N], gr[N];
    float g_t[N];
#pragma unroll
    for (int i = 0; i < N; i++) {
        int row = grp[i];
        p[i]  = si[SI_POS + row];
        tt[i] = si[SI_T + row];
        gr[i] = si[SI_GROW + row];
        long long bt = (long long)tt[i] * BSZ + gr[i];
        float u = (lane < NVOCAB) ? __ldg(&noise_tok[bt * NVOCAB + lane]) : 0.5f;
        g_t[i] = gumbelf(u);   // overlaps GEMV below
    }

    // Phase A on the old prefix, in sub-calls of 4/2 with in-call duplicate pad
    if (nold > 0) {
        if (N >= 5 && nold >= 5) {
            { int g4[4] = { grp[0], grp[1], grp[2], grp[3] }; phaseA<4>(sm, g4, lane); }
            if (nold == 6) { int g2[2] = { grp[4], grp[5] }; phaseA<2>(sm, g2, lane); }
            else           { int g2[2] = { grp[4], grp[4] }; phaseA<2>(sm, g2, lane); }
        } else if (N >= 3 && nold >= 3) {
            if (nold >= 4) { int g4[4] = { grp[0], grp[1], grp[2], grp[3] }; phaseA<4>(sm, g4, lane); }
            else           { int g4[4] = { grp[0], grp[1], grp[2], grp[0] }; phaseA<4>(sm, g4, lane); }
        } else {
            if (nold == 2) { int g2[2] = { grp[0], grp[1] }; phaseA<2>(sm, g2, lane); }
            else           { int g2[2] = { grp[0], grp[0] }; phaseA<2>(sm, g2, lane); }
        }
    }

    // Phase B: token head logits (lane = vocab index), N-way amortized
    u64 tkp[N];
#pragma unroll
    for (int i = 0; i < N; i++) tkp[i] = 0ull;
#pragma unroll 4
    for (int kq = 0; kq < 32; kq++) {
        u64 w01, w23;
        lds2(w01, w23, sm + S_TOKP + (kq * 32 + lane) * 4);
#pragma unroll
        for (int i = 0; i < N; i++) {
            u64 h01, h23;
            lds2(h01, h23, sm + S_H + grp[i] * HIDN + 4 * kq);
            tkp[i] = ffma2(h01, w01, tkp[i]);
            tkp[i] = ffma2(h23, w23, tkp[i]);
        }
    }
    float btok = sm[S_BTOK + lane];
    const float NEGINF = -INFINITY;

    // Phase C1: batched softmax + Gumbel argmax (redux-based, 1-round reductions)
    float ltok[N];
#pragma unroll
    for (int i = 0; i < N; i++) {
        float l = NEGINF;
        if (lane < NVOCAB) {
            l = f2lo(tkp[i]) + f2hi(tkp[i]) + btok;
            if (p[i] >= 15 && lane < 6) l = NEGINF;
        }
        ltok[i] = l;
    }
    float mx[N];
#pragma unroll
    for (int i = 0; i < N; i++) mx[i] = rmaxf(ltok[i]);
    float sme[N];
#pragma unroll
    for (int i = 0; i < N; i++)
        sme[i] = (lane < NVOCAB) ? expf(ltok[i] - mx[i]) : 0.f;
    // fixed-point warp sum: e in [0,1], <=19 terms, scale 2^25 -> no overflow.
    // lse error ~1e-6 is a COMMON shift across vocab lanes -> argmax unaffected.
    float ssum[N];
#pragma unroll
    for (int i = 0; i < N; i++)
        ssum[i] = rsumf(sme[i], 33554432.0f, 2.9802322387695312e-8f);
    float lpt[N], sc[N];
#pragma unroll
    for (int i = 0; i < N; i++) {
        float lse = logf(ssum[i]);
        lpt[i] = ltok[i] - mx[i] - lse;
        sc[i]  = lpt[i] + g_t[i];
    }
    float scm[N];
#pragma unroll
    for (int i = 0; i < N; i++) scm[i] = rmaxf(sc[i]);
    int ci[N];
    float lpw[N];
#pragma unroll
    for (int i = 0; i < N; i++) {
        unsigned b = __ballot_sync(FULLM, sc[i] == scm[i]);
        int widx = __ffs(b) - 1;        // first (lowest-index) max = jnp.argmax
        ci[i]  = widx;
        lpw[i] = __shfl_sync(FULLM, lpt[i], widx);
    }

    // Phase C2: rare const head + bookkeeping (only real rows)
    unsigned alive = 0;
#pragma unroll
    for (int i = 0; i < N; i++) {
        if (i >= rcnt) break;
        int row = grp[i];
        int pi  = p[i];
        int choice = ci[i];
        float lp_tok = lpw[i];

        bool is_const = (choice == 18);
        float lp_c = 0.f; int cchoice = 0;
        if (is_const) {   // warp-uniform
            float2 co = make_float2(0.f, 0.f);
#pragma unroll 8
            for (int k4 = 0; k4 < 32; k4++) {
                float4 hv = *(const float4*)(sm + S_H + row * HIDN + 4 * k4);
#pragma unroll
                for (int b = 0; b < 4; b++) {
                    float2 wc = *(const float2*)(sm + S_CON + (4 * k4 + b) * 64 + 2 * lane);
                    float hk = (b == 0) ? hv.x : (b == 1) ? hv.y : (b == 2) ? hv.z : hv.w;
                    co.x = fmaf(hk, wc.x, co.x);
                    co.y = fmaf(hk, wc.y, co.y);
                }
            }
            long long bt = (long long)tt[i] * BSZ + gr[i];
            float2 uc = make_float2(0.f, 0.f);
            if (lane < 20) uc = *(const float2*)(&noise_c[bt * NCONST + 2 * lane]);
            float bc0 = sm[S_BCON + 2 * lane];
            float bc1 = sm[S_BCON + 2 * lane + 1];
            float la = (lane < 20) ? (co.x + bc0) : NEGINF;
            float lb = (lane < 20) ? (co.y + bc1) : NEGINF;
            float mc   = rmaxf(fmaxf(la, lb));
            float ec   = (lane < 20) ? (expf(la - mc) + expf(lb - mc)) : 0.f;
            // e<=2/lane, 20 lanes -> sum<=40; scale 2^24 (40*2^24 < 2^31)
            float esum = rsumf(ec, 16777216.0f, 5.9604644775390625e-8f);
            float lsec = logf(esum);
            float lpa = la - mc - lsec;
            float lpb = lb - mc - lsec;
            float sa = lpa + gumbelf(uc.x);
            float sb = lpb + gumbelf(uc.y);
            // within-lane pick (tie -> lower index), then cross-lane first-max
            float s_l, lp_l; int i_l;
            if (sb > sa) { s_l = sb; i_l = 2 * lane + 1; lp_l = lpb; }
            else         { s_l = sa; i_l = 2 * lane;     lp_l = lpa; }
            float m2 = rmaxf(s_l);
            unsigned b2 = __ballot_sync(FULLM, s_l == m2);
            int wl = __ffs(b2) - 1;     // lowest lane among maxes = lowest index
            cchoice = __shfl_sync(FULLM, i_l, wl);
            lp_c    = __shfl_sync(FULLM, lp_l, wl);
        }

        if (lane == 0) {
            float lpn = sm[S_LP + row] + lp_tok + (is_const ? lp_c : 0.f);
            out[gr[i] * TT + pi] = (float)choice;
            if (is_const) out[OUT_CV + gr[i] * TT + pi] = -10.f + 0.5f * (float)cchoice;
            int arity = (choice < 4) ? 2 : ((choice < 6) ? 1 : 0);
            int sp = si[SI_SP + row];
            if (arity == 2) {
                int wsp = sp < 7 ? sp : 7;
                si[SI_STK + row * 8 + wsp] = 2 * pi + 2;
            }
            int sp1 = sp + (arity == 2 ? 1 : 0);
            int nxt, sp2;
            if (arity != 0) { nxt = 2 * pi + 1; sp2 = sp1; }
            else {
                int ridx = sp1 - 1; if (ridx < 0) ridx = 0; if (ridx > 7) ridx = 7;
                nxt = (sp1 > 0) ? si[SI_STK + row * 8 + ridx] : -1;
                sp2 = (sp1 > 0) ? sp1 - 1 : 0;
            }
            if (nxt > TT - 1) nxt = -1;
            if (nxt >= 0) {
                alive |= (1u << i);
                sm[S_LP + row]   = lpn;
                si[SI_POS + row] = nxt;
                si[SI_SP + row]  = sp2;
                si[SI_T + row]   = tt[i] + 1;
            } else {
                si[SI_ACT + row] = 0;
                out[OUT_LP + gr[i]] = lpn;
            }
        }
        if (choice & 15) {
            int cb = 4 * pi;
#pragma unroll
            for (int m = 0; m < 4; m++) {
                int j = lane + 32 * m;
                float a = sm[S_ACC + row * HIDN + j];
#pragma unroll
                for (int b = 0; b < 4; b++)
                    if (choice & (1 << b))
                        a += __ldg(&g_WihT[(cb + b) * HIDN + j]);
                sm[S_ACC + row * HIDN + j] = a;
            }
        }
    }
    alive = __shfl_sync(FULLM, alive, 0);
    __syncwarp();
    return alive;
}

__device__ __forceinline__ unsigned run_n(int n, int nol, float* sm, int* si,
        const float* nt, const float* nc, float* out, const int* grp, int lane)
{
    if (n > 4)      return superstep<6>(sm, si, nt, nc, out, grp, n, nol, lane);
    else if (n > 2) return superstep<4>(sm, si, nt, nc, out, grp, n, nol, lane);
    else            return superstep<2>(sm, si, nt, nc, out, grp, n, nol, lane);
}

__global__ void __launch_bounds__(NTH, 1)
rnn_main(const float* __restrict__ x,
         const float* __restrict__ noise_tok,
         const float* __restrict__ noise_c,
         const float* __restrict__ W_ih,
         const float* __restrict__ W_hh,
         const float* __restrict__ b_ih,
         const float* __restrict__ b_hh,
         const float* __restrict__ W_out,
         const float* __restrict__ b_out,
         const float* __restrict__ W_c,
         const float* __restrict__ b_c,
         float* __restrict__ out)
{
    extern __shared__ float sm[];
    int* si = (int*)(sm + S_NF);
    int tid = threadIdx.x;
    int w = tid >> 5, lane = tid & 31;

    // ---- stage weights ----
    {
        const float4* src = (const float4*)W_hh;   // [j][32]
        float4* dst = (float4*)(sm + S_WHH);
        for (int idx = tid; idx < 32 * 128; idx += NTH) {
            int kq = idx >> 7, j = idx & 127;
            dst[kq * 128 + j] = src[j * 32 + kq];
        }
    }
    {
        float4* dst = (float4*)(sm + S_TOKP);
        const float4 z4 = make_float4(0.f, 0.f, 0.f, 0.f);
        const float4* src = (const float4*)W_out;  // [v][32]
        for (int idx = tid; idx < 32 * 32; idx += NTH) {
            int kq = idx >> 5, v = idx & 31;
            dst[kq * 32 + v] = (v < NVOCAB) ? src[v * 32 + kq] : z4;
        }
    }
    for (int idx = tid; idx < HIDN * 64; idx += NTH) sm[S_CON + idx] = 0.f;
    __syncthreads();
    for (int idx = tid; idx < NCONST * HIDN; idx += NTH) {
        int c = idx / HIDN, k = idx % HIDN;
        sm[S_CON + k * 64 + c] = W_c[idx];
    }
    for (int idx = tid; idx < 9 * HIDN; idx += NTH) {
        int f = idx >> 7, j = idx & 127;
        sm[S_WX + f * 128 + j] = W_ih[j * INSZ + 124 + f];
    }
    if (tid < HIDN) sm[S_BSUM + tid] = b_ih[tid] + b_hh[tid];
    if (tid < 32) sm[S_BTOK + tid] = (tid < NVOCAB) ? b_out[tid] : 0.f;
    if (tid < 64) sm[S_BCON + tid] = (tid < NCONST) ? b_c[tid] : 0.f;
    if (tid < SLOTS) si[SI_ACT + tid] = 0;
    __syncthreads();

    // ---- persistent work loop (2 barriers per round) ----
    for (;;) {
        if (w == 0) {
            unsigned lt = (1u << lane) - 1u;
            int nold = 0, ndead = 0;
            unsigned am[3];
            int po[3], pd[3];
#pragma unroll
            for (int c = 0; c < 3; c++) {
                int act = si[SI_ACT + 32 * c + lane];
                unsigned m = __ballot_sync(FULLM, act != 0);
                am[c] = m; po[c] = nold; pd[c] = ndead;
                nold  += __popc(m);
                ndead += 32 - __popc(m);
            }
            int base = 0;
            if (lane == 0 && ndead > 0) base = atomicAdd(&g_next, ndead);
            base = __shfl_sync(FULLM, base, 0);
            int navail = BSZ - base;
            if (navail < 0) navail = 0;
            if (navail > ndead) navail = ndead;
#pragma unroll
            for (int c = 0; c < 3; c++) {
                int slot = 32 * c + lane;
                if ((am[c] >> lane) & 1) si[SI_LIST + po[c] + __popc(am[c] & lt)] = slot;
                else                     si[SI_DEAD + pd[c] + __popc(~am[c] & lt)] = slot;
            }
            __syncwarp();
            for (int q = lane; q < navail; q += 32)
                si[SI_LIST + nold + q] = si[SI_DEAD + q];
            if (lane == 0) {
                si[SI_CNT]     = nold + navail;
                si[SI_CNT + 1] = navail;
                si[SI_CNT + 2] = (ndead > 0) ? base : 0;
                si[SI_CNT + 3] = nold;
            }
        }
        __syncthreads();
        int A = si[SI_CNT];
        int navail = si[SI_CNT + 1];
        int rbase  = si[SI_CNT + 2];
        int oldc   = si[SI_CNT + 3];
        if (A == 0) break;
        bool drain = (navail == 0) && (rbase >= BSZ);   // pool empty forever

        // this warp's contiguous chunk of the active list
        int lo = (A * w) >> 4;
        int hi = (A * (w + 1)) >> 4;

        // owner-refill: init this warp's fresh rows (h = tanh(acc); step-0 GEMV = 0)
        int fstart = lo > oldc ? lo : oldc;
        for (int idx = fstart; idx < hi; idx++) {
            int slot = si[SI_LIST + idx];
            int gr = rbase + (idx - oldc);
            float xv[9];
#pragma unroll
            for (int f = 0; f < 9; f++) xv[f] = __ldg(&x[gr * 9 + f]);
#pragma unroll
            for (int m = 0; m < 4; m++) {
                int j = lane + 32 * m;
                float a = sm[S_BSUM + j];
#pragma unroll
                for (int f = 0; f < 9; f++) a = fmaf(xv[f], sm[S_WX + f * 128 + j], a);
                sm[S_ACC + slot * HIDN + j] = a;
                sm[S_H + slot * HIDN + j] = tanhf(a);
            }
            // default-init this row's output slice (each row refilled exactly once)
            if (lane < TT) {
                out[gr * TT + lane] = -1.f;
                out[OUT_CV + gr * TT + lane] = 0.f;
            }
            if (lane == 0) {
                si[SI_POS + slot]  = 0;
                si[SI_SP + slot]   = 0;
                si[SI_T + slot]    = 0;
                si[SI_ACT + slot]  = 1;
                si[SI_GROW + slot] = gr;
                sm[S_LP + slot]    = 0.f;
            }
        }
        __syncwarp();

        // super-steps of up to 6 rows
        for (int base = lo; base < hi; base += 6) {
            int n = hi - base; if (n > 6) n = 6;
            int grp[6];
#pragma unroll
            for (int q = 0; q < 6; q++)
                grp[q] = si[SI_LIST + base + (q < n ? q : 0)];
            int nol = oldc - base;
            if (nol < 0) nol = 0;
            if (nol > n) nol = n;
            unsigned mv = run_n(n, nol, sm, si, noise_tok, noise_c, out, grp, lane);

            // drain mode: run this chunk's survivors to completion, no barriers
            while (drain && mv) {
                int ag[6]; int cnt = 0;
                for (int q = 0; q < n; q++)
                    if ((mv >> q) & 1) ag[cnt++] = grp[q];
                n = cnt;
                for (int q = 0; q < 6; q++) grp[q] = ag[q < n ? q : 0];
                mv = run_n(n, n, sm, si, noise_tok, noise_c, out, grp, lane);
            }
        }
        __syncthreads();
        if (drain) break;   // all remaining rows ran to completion above
    }
}

// prep only (out-init handled per-row at refill time)
__global__ void setup_kernel(const float* __restrict__ W_ih)
{
    int i = blockIdx.x * blockDim.x + threadIdx.x;
    if (i == 0) g_next = 0;
    if (i < INSZ * HIDN) {
        int c = i / HIDN, j = i % HIDN;
        g_WihT[c * HIDN + j] = W_ih[j * INSZ + c];
    }
}

extern "C" void kernel_launch(void* const* d_in, const int* in_sizes, int n_in,
                              void* d_out, int out_size)
{
    const float* x    = (const float*)d_in[0];
    const float* nt   = (const float*)d_in[1];
    const float* nc   = (const float*)d_in[2];
    const float* wih  = (const float*)d_in[3];
    const float* whh  = (const float*)d_in[4];
    const float* bih  = (const float*)d_in[5];
    const float* bhh  = (const float*)d_in[6];
    const float* wout = (const float*)d_in[7];
    const float* bout = (const float*)d_in[8];
    const float* wc   = (const float*)d_in[9];
    const float* bc   = (const float*)d_in[10];
    float* out = (float*)d_out;

    cudaFuncSetAttribute((const void*)rnn_main,
                         cudaFuncAttributeMaxDynamicSharedMemorySize, SMEM_BYTES);
    setup_kernel<<<(INSZ * HIDN + 255) / 256, 256>>>(wih);
    rnn_main<<<NBLK, NTH, SMEM_BYTES>>>(x, nt, nc, wih, whh, bih, bhh,
                                        wout, bout, wc, bc, out);
}